// round 2
// baseline (speedup 1.0000x reference)
#include <cuda_runtime.h>
#include <math.h>

#define NN 50000
#define EE 150000
#define RR 3
#define LL 2
#define HH 512
#define NHEADS 8
#define DHH 64
#define NCLSS 23

// ---------------- scratch (device globals; no allocs allowed) ----------------
__device__ float g_h[(size_t)NN * HH];
__device__ float g_tmp[(size_t)NN * HH];
__device__ float g_f[(size_t)NN * HH];
__device__ float g_agg[(size_t)NN * HH];
__device__ float g_stk[(size_t)NN * RR * HH];
__device__ float g_q[(size_t)NN * RR * HH];
__device__ float g_k[(size_t)NN * RR * HH];
__device__ float g_v[(size_t)NN * RR * HH];
__device__ float g_rdo[(size_t)RR * NN];
__device__ float g_rdi[(size_t)RR * NN];
__device__ float g_el[(size_t)NN * NHEADS];
__device__ float g_er[(size_t)NN * NHEADS];
__device__ float g_m[(size_t)NN * NHEADS];
__device__ float g_s[(size_t)NN * NHEADS];
__device__ float g_e[(size_t)EE * NHEADS];

// ---------------- helpers ----------------
__device__ __forceinline__ void atomicMaxFloat(float* addr, float val) {
    if (val >= 0.0f) {
        atomicMax((int*)addr, __float_as_int(val));
    } else {
        atomicMin((unsigned int*)addr, (unsigned int)__float_as_int(val));
    }
}

__device__ __forceinline__ float block_reduce_sum_128(float val) {
    __shared__ float sh[32];
    __syncthreads();  // protect sh reuse across calls
    int lane = threadIdx.x & 31;
    int wid = threadIdx.x >> 5;
#pragma unroll
    for (int o = 16; o > 0; o >>= 1) val += __shfl_xor_sync(0xffffffffu, val, o);
    if (lane == 0) sh[wid] = val;
    __syncthreads();
    if (wid == 0) {
        float v = (lane < (blockDim.x >> 5)) ? sh[lane] : 0.0f;
#pragma unroll
        for (int o = 16; o > 0; o >>= 1) v += __shfl_xor_sync(0xffffffffu, v, o);
        if (lane == 0) sh[0] = v;
    }
    __syncthreads();
    return sh[0];
}

// ---------------- degree kernels ----------------
__global__ void degree_count(const int* __restrict__ src, const int* __restrict__ dst,
                             float* __restrict__ rdo, float* __restrict__ rdi) {
    int idx = blockIdx.x * blockDim.x + threadIdx.x;
    if (idx >= RR * EE) return;
    int r = idx / EE;
    atomicAdd(&rdo[(size_t)r * NN + src[idx]], 1.0f);
    atomicAdd(&rdi[(size_t)r * NN + dst[idx]], 1.0f);
}

__global__ void degree_finalize(float* __restrict__ p, int n) {
    int idx = blockIdx.x * blockDim.x + threadIdx.x;
    if (idx < n) p[idx] = rsqrtf(fmaxf(p[idx], 1.0f));
}

// ---------------- SGEMM: C[M,512] = A[M,512] @ W[512,512] (* rowscale) (+ bias) ---------
// 128x128 tile, BK=16, 256 threads, 8x8 per thread in 2x2 sub-fragment layout.
__global__ __launch_bounds__(256) void sgemm512(
    const float* __restrict__ A, const float* __restrict__ W,
    float* __restrict__ C, int M,
    const float* __restrict__ rowscale, const float* __restrict__ bias) {
    __shared__ float As[16][128];
    __shared__ float Bs[16][128];
    const int bm = blockIdx.y * 128;
    const int bn = blockIdx.x * 128;
    const int tid = threadIdx.x;
    const int tx = tid & 15;
    const int ty = tid >> 4;
    float acc[8][8];
#pragma unroll
    for (int i = 0; i < 8; i++)
#pragma unroll
        for (int j = 0; j < 8; j++) acc[i][j] = 0.0f;

    for (int k0 = 0; k0 < 512; k0 += 16) {
        // A tile: 128 rows x 16 cols = 512 float4 slots
#pragma unroll
        for (int i = 0; i < 2; i++) {
            int slot = tid + i * 256;
            int row = slot >> 2;
            int c4 = slot & 3;
            float4 val = make_float4(0.f, 0.f, 0.f, 0.f);
            int gr = bm + row;
            if (gr < M) val = *(const float4*)(A + (size_t)gr * 512 + k0 + c4 * 4);
            As[c4 * 4 + 0][row] = val.x;
            As[c4 * 4 + 1][row] = val.y;
            As[c4 * 4 + 2][row] = val.z;
            As[c4 * 4 + 3][row] = val.w;
        }
        // W tile: 16 rows x 128 cols = 512 float4 slots
#pragma unroll
        for (int i = 0; i < 2; i++) {
            int slot = tid + i * 256;
            int kk = slot >> 5;
            int j4 = slot & 31;
            float4 val = *(const float4*)(W + (size_t)(k0 + kk) * 512 + bn + j4 * 4);
            *(float4*)(&Bs[kk][j4 * 4]) = val;
        }
        __syncthreads();
#pragma unroll
        for (int kk = 0; kk < 16; kk++) {
            float ra[8], rb[8];
            // rows: ty*4..+3 and 64+ty*4..+3 ; cols: tx*4..+3 and 64+tx*4..+3
            float4 a0 = *(const float4*)(&As[kk][ty * 4]);
            float4 a1 = *(const float4*)(&As[kk][64 + ty * 4]);
            float4 b0 = *(const float4*)(&Bs[kk][tx * 4]);
            float4 b1 = *(const float4*)(&Bs[kk][64 + tx * 4]);
            ra[0] = a0.x; ra[1] = a0.y; ra[2] = a0.z; ra[3] = a0.w;
            ra[4] = a1.x; ra[5] = a1.y; ra[6] = a1.z; ra[7] = a1.w;
            rb[0] = b0.x; rb[1] = b0.y; rb[2] = b0.z; rb[3] = b0.w;
            rb[4] = b1.x; rb[5] = b1.y; rb[6] = b1.z; rb[7] = b1.w;
#pragma unroll
            for (int i = 0; i < 8; i++)
#pragma unroll
                for (int j = 0; j < 8; j++) acc[i][j] += ra[i] * rb[j];
        }
        __syncthreads();
    }
#pragma unroll
    for (int i = 0; i < 8; i++) {
        int gr = bm + ((i < 4) ? (ty * 4 + i) : (64 + ty * 4 + i - 4));
        if (gr >= M) continue;
        float sc = rowscale ? rowscale[gr] : 1.0f;
#pragma unroll
        for (int j = 0; j < 8; j++) {
            int gc = bn + ((j < 4) ? (tx * 4 + j) : (64 + tx * 4 + j - 4));
            float val = acc[i][j] * sc;
            if (bias) val += bias[gc];
            C[(size_t)gr * 512 + gc] = val;
        }
    }
}

// ---------------- LayerNorm + ELU + write/accumulate into stacked slot -------
// X: [N,H]; out points at g_stk + r*HH; row stride RR*HH.
__global__ __launch_bounds__(128) void ln_elu_acc(
    const float* __restrict__ X, const float* __restrict__ rdi,
    const float* __restrict__ bias, const float* __restrict__ gamma,
    const float* __restrict__ beta, float* __restrict__ out, int accumulate) {
    int n = blockIdx.x;
    const float* x = X + (size_t)n * HH;
    float sc = rdi ? rdi[n] : 1.0f;
    float v[4];
    float sum = 0.0f;
#pragma unroll
    for (int i = 0; i < 4; i++) {
        int j = threadIdx.x + i * 128;
        v[i] = x[j] * sc + bias[j];
        sum += v[i];
    }
    sum = block_reduce_sum_128(sum);
    float u = sum * (1.0f / HH);
    float var = 0.0f;
#pragma unroll
    for (int i = 0; i < 4; i++) {
        float d = v[i] - u;
        var += d * d;
    }
    var = block_reduce_sum_128(var) * (1.0f / HH);
    float inv = rsqrtf(var + 1e-12f);
#pragma unroll
    for (int i = 0; i < 4; i++) {
        int j = threadIdx.x + i * 128;
        float y = gamma[j] * (v[i] - u) * inv + beta[j];
        y = (y > 0.0f) ? y : (expf(y) - 1.0f);
        float* o = out + (size_t)n * (RR * HH) + j;
        if (accumulate) *o += y; else *o = y;
    }
}

// ---------------- zero / init ----------------
__global__ void zero_f32(float* __restrict__ p, long long n) {
    long long idx = (long long)blockIdx.x * blockDim.x + threadIdx.x;
    long long stride = (long long)gridDim.x * blockDim.x;
    for (; idx < n; idx += stride) p[idx] = 0.0f;
}

__global__ void init_ms(float* __restrict__ m, float* __restrict__ s) {
    int idx = blockIdx.x * blockDim.x + threadIdx.x;
    if (idx < NN * NHEADS) { m[idx] = -INFINITY; s[idx] = 0.0f; }
}

// ---------------- GraphConv scatter: agg[dst] += X[src] ----------------
__global__ void conv_scatter(const int* __restrict__ src, const int* __restrict__ dst,
                             const float* __restrict__ X, float* __restrict__ agg) {
    long long idx = (long long)blockIdx.x * blockDim.x + threadIdx.x;
    if (idx >= (long long)EE * HH) return;
    int e = (int)(idx >> 9);
    int j = (int)(idx & 511);
    atomicAdd(&agg[(size_t)dst[e] * HH + j], X[(size_t)src[e] * HH + j]);
}

// ---------------- GAT ----------------
__global__ void gat_el_er(const float* __restrict__ f, const float* __restrict__ al,
                          const float* __restrict__ ar, float* __restrict__ el,
                          float* __restrict__ er) {
    int idx = blockIdx.x * blockDim.x + threadIdx.x;
    if (idx >= NN * NHEADS) return;
    int n = idx >> 3;
    int hh = idx & 7;
    const float* fr = f + (size_t)n * HH + hh * DHH;
    const float* a1 = al + hh * DHH;
    const float* a2 = ar + hh * DHH;
    float s1 = 0.0f, s2 = 0.0f;
#pragma unroll 8
    for (int d = 0; d < DHH; d++) {
        float fv = fr[d];
        s1 += fv * a1[d];
        s2 += fv * a2[d];
    }
    el[idx] = s1;
    er[idx] = s2;
}

__global__ void gat_edge1(const int* __restrict__ src, const int* __restrict__ dst,
                          const float* __restrict__ el, const float* __restrict__ er,
                          float* __restrict__ e, float* __restrict__ m) {
    int idx = blockIdx.x * blockDim.x + threadIdx.x;
    if (idx >= EE * NHEADS) return;
    int ed = idx >> 3;
    int hh = idx & 7;
    float x = el[src[ed] * NHEADS + hh] + er[dst[ed] * NHEADS + hh];
    x = (x > 0.0f) ? x : 0.2f * x;  // leaky_relu 0.2
    e[idx] = x;
    atomicMaxFloat(&m[dst[ed] * NHEADS + hh], x);
}

__global__ void gat_edge2(const int* __restrict__ dst, float* __restrict__ e,
                          const float* __restrict__ m, float* __restrict__ s) {
    int idx = blockIdx.x * blockDim.x + threadIdx.x;
    if (idx >= EE * NHEADS) return;
    int ed = idx >> 3;
    int hh = idx & 7;
    float ex = expf(e[idx] - m[dst[ed] * NHEADS + hh]);
    e[idx] = ex;
    atomicAdd(&s[dst[ed] * NHEADS + hh], ex);
}

__global__ void gat_edge3(const int* __restrict__ src, const int* __restrict__ dst,
                          const float* __restrict__ e, const float* __restrict__ s,
                          const float* __restrict__ f, float* __restrict__ agg) {
    long long idx = (long long)blockIdx.x * blockDim.x + threadIdx.x;
    if (idx >= (long long)EE * HH) return;
    int ed = (int)(idx >> 9);
    int j = (int)(idx & 511);
    int hh = j >> 6;
    int dn = dst[ed];
    float sv = s[dn * NHEADS + hh];
    float alpha = e[ed * NHEADS + hh] / ((sv > 0.0f) ? sv : 1.0f);
    atomicAdd(&agg[(size_t)dn * HH + j], alpha * f[(size_t)src[ed] * HH + j]);
}

// ---------------- relation MHA (3 tokens) + mean over tokens ----------------
// warp per (node, head); writes out[n, head*64 + d]
__global__ __launch_bounds__(256) void mha_mean(
    const float* __restrict__ q, const float* __restrict__ k,
    const float* __restrict__ v, float* __restrict__ out) {
    int n = blockIdx.x;
    int hd = threadIdx.x >> 5;
    int lane = threadIdx.x & 31;
    size_t base = (size_t)n * RR * HH + hd * DHH;
    float qa[RR], qb[RR], ka[RR], kb[RR], va[RR], vb[RR];
#pragma unroll
    for (int r = 0; r < RR; r++) {
        size_t off = base + (size_t)r * HH;
        qa[r] = q[off + lane];
        qb[r] = q[off + lane + 32];
        ka[r] = k[off + lane];
        kb[r] = k[off + lane + 32];
        va[r] = v[off + lane];
        vb[r] = v[off + lane + 32];
    }
    float sc[RR][RR];
#pragma unroll
    for (int r = 0; r < RR; r++)
#pragma unroll
        for (int t = 0; t < RR; t++) {
            float p = qa[r] * ka[t] + qb[r] * kb[t];
#pragma unroll
            for (int o = 16; o > 0; o >>= 1) p += __shfl_xor_sync(0xffffffffu, p, o);
            sc[r][t] = p * 0.125f;  // 1/sqrt(64)
        }
    float w0 = 0.0f, w1 = 0.0f, w2 = 0.0f;
#pragma unroll
    for (int r = 0; r < RR; r++) {
        float mx = fmaxf(sc[r][0], fmaxf(sc[r][1], sc[r][2]));
        float e0 = expf(sc[r][0] - mx);
        float e1 = expf(sc[r][1] - mx);
        float e2 = expf(sc[r][2] - mx);
        float inv = 1.0f / (e0 + e1 + e2);
        w0 += e0 * inv;
        w1 += e1 * inv;
        w2 += e2 * inv;
    }
    const float third = 1.0f / 3.0f;
    float oa = (w0 * va[0] + w1 * va[1] + w2 * va[2]) * third;
    float ob = (w0 * vb[0] + w1 * vb[1] + w2 * vb[2]) * third;
    out[(size_t)n * HH + hd * DHH + lane] = oa;
    out[(size_t)n * HH + hd * DHH + lane + 32] = ob;
}

// ---------------- classifier ----------------
__global__ void classify(const float* __restrict__ h, const float* __restrict__ W,
                         const float* __restrict__ b, float* __restrict__ out) {
    int idx = blockIdx.x * blockDim.x + threadIdx.x;
    if (idx >= NN * NCLSS) return;
    int n = idx / NCLSS;
    int c = idx % NCLSS;
    const float* hr = h + (size_t)n * HH;
    float sum = b[c];
#pragma unroll 8
    for (int j = 0; j < HH; j++) sum += hr[j] * W[j * NCLSS + c];
    out[idx] = sum;
}

// ---------------- launch ----------------
extern "C" void kernel_launch(void* const* d_in, const int* in_sizes, int n_in,
                              void* d_out, int out_size) {
    const float* feature = (const float*)d_in[0];
    const int* src = (const int*)d_in[1];
    const int* dst = (const int*)d_in[2];
    const float* Wc = (const float*)d_in[3];
    const float* bc = (const float*)d_in[4];
    const float* gc = (const float*)d_in[5];
    const float* betac = (const float*)d_in[6];
    const float* Wg = (const float*)d_in[7];
    const float* bg = (const float*)d_in[8];
    const float* al = (const float*)d_in[9];
    const float* ar = (const float*)d_in[10];
    const float* gg = (const float*)d_in[11];
    const float* betag = (const float*)d_in[12];
    const float* Ws = (const float*)d_in[13];
    const float* bs = (const float*)d_in[14];
    const float* gs = (const float*)d_in[15];
    const float* betas = (const float*)d_in[16];
    const float* Wq = (const float*)d_in[17];
    const float* bq = (const float*)d_in[18];
    const float* Wk = (const float*)d_in[19];
    const float* bk = (const float*)d_in[20];
    const float* Wv = (const float*)d_in[21];
    const float* bv = (const float*)d_in[22];
    const float* Wout = (const float*)d_in[23];
    const float* bout = (const float*)d_in[24];
    float* out = (float*)d_out;

    float *p_h, *p_tmp, *p_f, *p_agg, *p_stk, *p_q, *p_k, *p_v;
    float *p_rdo, *p_rdi, *p_el, *p_er, *p_m, *p_s, *p_e;
    cudaGetSymbolAddress((void**)&p_h, g_h);
    cudaGetSymbolAddress((void**)&p_tmp, g_tmp);
    cudaGetSymbolAddress((void**)&p_f, g_f);
    cudaGetSymbolAddress((void**)&p_agg, g_agg);
    cudaGetSymbolAddress((void**)&p_stk, g_stk);
    cudaGetSymbolAddress((void**)&p_q, g_q);
    cudaGetSymbolAddress((void**)&p_k, g_k);
    cudaGetSymbolAddress((void**)&p_v, g_v);
    cudaGetSymbolAddress((void**)&p_rdo, g_rdo);
    cudaGetSymbolAddress((void**)&p_rdi, g_rdi);
    cudaGetSymbolAddress((void**)&p_el, g_el);
    cudaGetSymbolAddress((void**)&p_er, g_er);
    cudaGetSymbolAddress((void**)&p_m, g_m);
    cudaGetSymbolAddress((void**)&p_s, g_s);
    cudaGetSymbolAddress((void**)&p_e, g_e);

    cudaMemcpyAsync(p_h, feature, (size_t)NN * HH * sizeof(float),
                    cudaMemcpyDeviceToDevice, 0);

    // degrees (same graph for both layers)
    cudaMemsetAsync(p_rdo, 0, (size_t)RR * NN * sizeof(float), 0);
    cudaMemsetAsync(p_rdi, 0, (size_t)RR * NN * sizeof(float), 0);
    degree_count<<<(RR * EE + 255) / 256, 256>>>(src, dst, p_rdo, p_rdi);
    degree_finalize<<<(RR * NN + 255) / 256, 256>>>(p_rdo, RR * NN);
    degree_finalize<<<(RR * NN + 255) / 256, 256>>>(p_rdi, RR * NN);

    const dim3 gemm_grid_n(4, (NN + 127) / 128);
    const dim3 gemm_grid_nr(4, (NN * RR + 127) / 128);
    const int eh_blocks = (int)(((long long)EE * HH + 255) / 256);
    const int ehd_blocks = (EE * NHEADS + 255) / 256;
    const int nhd_blocks = (NN * NHEADS + 255) / 256;

    for (int l = 0; l < LL; l++) {
        for (int r = 0; r < RR; r++) {
            const size_t lr = (size_t)(l * RR + r);
            const float* Wc_lr = Wc + lr * HH * HH;
            const float* Wg_lr = Wg + lr * HH * HH;
            const float* Ws_lr = Ws + lr * HH * HH;
            const float* bc_lr = bc + lr * HH;
            const float* gc_lr = gc + lr * HH;
            const float* betac_lr = betac + lr * HH;
            const float* bg_lr = bg + lr * HH;
            const float* gg_lr = gg + lr * HH;
            const float* betag_lr = betag + lr * HH;
            const float* bs_lr = bs + lr * HH;
            const float* gs_lr = gs + lr * HH;
            const float* betas_lr = betas + lr * HH;
            const float* al_lr = al + lr * NHEADS * DHH;
            const float* ar_lr = ar + lr * NHEADS * DHH;
            const int* src_r = src + (size_t)r * EE;
            const int* dst_r = dst + (size_t)r * EE;

            // ---- GraphConv ----
            sgemm512<<<gemm_grid_n, 256>>>(p_h, Wc_lr, p_tmp, NN,
                                           p_rdo + (size_t)r * NN, nullptr);
            cudaMemsetAsync(p_agg, 0, (size_t)NN * HH * sizeof(float), 0);
            conv_scatter<<<eh_blocks, 256>>>(src_r, dst_r, p_tmp, p_agg);
            ln_elu_acc<<<NN, 128>>>(p_agg, p_rdi + (size_t)r * NN, bc_lr, gc_lr,
                                    betac_lr, p_stk + (size_t)r * HH, 0);

            // ---- GATConv ----
            sgemm512<<<gemm_grid_n, 256>>>(p_h, Wg_lr, p_f, NN, nullptr, nullptr);
            gat_el_er<<<nhd_blocks, 256>>>(p_f, al_lr, ar_lr, p_el, p_er);
            init_ms<<<nhd_blocks, 256>>>(p_m, p_s);
            gat_edge1<<<ehd_blocks, 256>>>(src_r, dst_r, p_el, p_er, p_e, p_m);
            gat_edge2<<<ehd_blocks, 256>>>(dst_r, p_e, p_m, p_s);
            cudaMemsetAsync(p_agg, 0, (size_t)NN * HH * sizeof(float), 0);
            gat_edge3<<<eh_blocks, 256>>>(src_r, dst_r, p_e, p_s, p_f, p_agg);
            ln_elu_acc<<<NN, 128>>>(p_agg, nullptr, bg_lr, gg_lr, betag_lr,
                                    p_stk + (size_t)r * HH, 1);

            // ---- skip ----
            sgemm512<<<gemm_grid_n, 256>>>(p_h, Ws_lr, p_tmp, NN, nullptr, nullptr);
            ln_elu_acc<<<NN, 128>>>(p_tmp, nullptr, bs_lr, gs_lr, betas_lr,
                                    p_stk + (size_t)r * HH, 1);
        }

        // ---- relation MHA ----
        const float* Wq_l = Wq + (size_t)l * HH * HH;
        const float* Wk_l = Wk + (size_t)l * HH * HH;
        const float* Wv_l = Wv + (size_t)l * HH * HH;
        sgemm512<<<gemm_grid_nr, 256>>>(p_stk, Wq_l, p_q, NN * RR, nullptr,
                                        bq + (size_t)l * HH);
        sgemm512<<<gemm_grid_nr, 256>>>(p_stk, Wk_l, p_k, NN * RR, nullptr,
                                        bk + (size_t)l * HH);
        sgemm512<<<gemm_grid_nr, 256>>>(p_stk, Wv_l, p_v, NN * RR, nullptr,
                                        bv + (size_t)l * HH);
        mha_mean<<<NN, 256>>>(p_q, p_k, p_v, p_h);
    }

    classify<<<(NN * NCLSS + 255) / 256, 256>>>(p_h, Wout, bout, out);
}

// round 3
// speedup vs baseline: 1.8912x; 1.8912x over previous
#include <cuda_runtime.h>
#include <math.h>

#define NN 50000
#define EE 150000
#define RR 3
#define LL 2
#define HH 512
#define NHEADS 8
#define DHH 64
#define NCLSS 23

// ---------------- scratch (device globals; no allocs allowed) ----------------
__device__ float g_h[(size_t)NN * HH];
__device__ float g_tmp[(size_t)NN * HH];
__device__ float g_f[(size_t)NN * HH];
__device__ float g_agg[(size_t)NN * HH];
__device__ float g_stk[(size_t)NN * RR * HH];
__device__ float g_q[(size_t)NN * RR * HH];
__device__ float g_k[(size_t)NN * RR * HH];
__device__ float g_v[(size_t)NN * RR * HH];
__device__ float g_rdo[(size_t)RR * NN];
__device__ float g_rdi[(size_t)RR * NN];
__device__ float g_el[(size_t)NN * NHEADS];
__device__ float g_er[(size_t)NN * NHEADS];
__device__ float g_m[(size_t)NN * NHEADS];
__device__ float g_s[(size_t)NN * NHEADS];
__device__ float g_e[(size_t)EE * NHEADS];

// ---------------- helpers ----------------
__device__ __forceinline__ void atomicMaxFloat(float* addr, float val) {
    if (val >= 0.0f) {
        atomicMax((int*)addr, __float_as_int(val));
    } else {
        atomicMin((unsigned int*)addr, (unsigned int)__float_as_int(val));
    }
}

__device__ __forceinline__ float block_reduce_sum_128(float val) {
    __shared__ float sh[32];
    __syncthreads();
    int lane = threadIdx.x & 31;
    int wid = threadIdx.x >> 5;
#pragma unroll
    for (int o = 16; o > 0; o >>= 1) val += __shfl_xor_sync(0xffffffffu, val, o);
    if (lane == 0) sh[wid] = val;
    __syncthreads();
    if (wid == 0) {
        float v = (lane < (blockDim.x >> 5)) ? sh[lane] : 0.0f;
#pragma unroll
        for (int o = 16; o > 0; o >>= 1) v += __shfl_xor_sync(0xffffffffu, v, o);
        if (lane == 0) sh[0] = v;
    }
    __syncthreads();
    return sh[0];
}

__device__ __forceinline__ unsigned f2tf32(float x) {
    unsigned r;
    asm("cvt.rna.tf32.f32 %0, %1;" : "=r"(r) : "f"(x));
    return r;
}

__device__ __forceinline__ void mma_tf32(float* d, const unsigned* a, const unsigned* b) {
    asm volatile(
        "mma.sync.aligned.m16n8k8.row.col.f32.tf32.tf32.f32 "
        "{%0,%1,%2,%3}, {%4,%5,%6,%7}, {%8,%9}, {%0,%1,%2,%3};"
        : "+f"(d[0]), "+f"(d[1]), "+f"(d[2]), "+f"(d[3])
        : "r"(a[0]), "r"(a[1]), "r"(a[2]), "r"(a[3]), "r"(b[0]), "r"(b[1]));
}

// ---------------- degree kernels ----------------
__global__ void degree_count(const int* __restrict__ src, const int* __restrict__ dst,
                             float* __restrict__ rdo, float* __restrict__ rdi) {
    int idx = blockIdx.x * blockDim.x + threadIdx.x;
    if (idx >= RR * EE) return;
    int r = idx / EE;
    atomicAdd(&rdo[(size_t)r * NN + src[idx]], 1.0f);
    atomicAdd(&rdi[(size_t)r * NN + dst[idx]], 1.0f);
}

__global__ void degree_finalize(float* __restrict__ p, int n) {
    int idx = blockIdx.x * blockDim.x + threadIdx.x;
    if (idx < n) p[idx] = rsqrtf(fmaxf(p[idx], 1.0f));
}

// ---------------- TF32 tensor-core GEMM -------------------------------------
// C[M,512] = A[M,512] @ W[512,512] (* rowscale[row]) (+ bias[col])
// 128x128 block tile, BK=32, 256 threads = 8 warps (4 along M x 2 along N),
// warp tile 32x64, mma.sync.m16n8k8.tf32.
#define A_STRIDE 36
#define B_STRIDE 136
__global__ __launch_bounds__(256) void tf32gemm512(
    const float* __restrict__ A, const float* __restrict__ W,
    float* __restrict__ C, int M,
    const float* __restrict__ rowscale, const float* __restrict__ bias) {
    __shared__ unsigned As[128 * A_STRIDE];  // [row][k], padded
    __shared__ unsigned Bs[32 * B_STRIDE];   // [k][n], padded

    const int bm = blockIdx.y * 128;
    const int bn = blockIdx.x * 128;
    const int tid = threadIdx.x;
    const int warp = tid >> 5;
    const int lane = tid & 31;
    const int g = lane >> 2;   // group id 0..7
    const int t = lane & 3;    // thread in group 0..3
    const int wm = (warp >> 1) * 32;  // warp M offset 0,32,64,96
    const int wn = (warp & 1) * 64;   // warp N offset 0,64

    float acc[2][8][4];
#pragma unroll
    for (int i = 0; i < 2; i++)
#pragma unroll
        for (int j = 0; j < 8; j++)
#pragma unroll
            for (int q = 0; q < 4; q++) acc[i][j][q] = 0.0f;

    for (int k0 = 0; k0 < 512; k0 += 32) {
        // load A tile: 128 rows x 32 k = 1024 float4 slots
#pragma unroll
        for (int i = 0; i < 4; i++) {
            int slot = tid + i * 256;
            int row = slot >> 3;
            int c4 = slot & 7;
            float4 val = make_float4(0.f, 0.f, 0.f, 0.f);
            int gr = bm + row;
            if (gr < M) val = *(const float4*)(A + (size_t)gr * 512 + k0 + c4 * 4);
            unsigned* p = &As[row * A_STRIDE + c4 * 4];
            p[0] = f2tf32(val.x);
            p[1] = f2tf32(val.y);
            p[2] = f2tf32(val.z);
            p[3] = f2tf32(val.w);
        }
        // load B tile: 32 k x 128 n = 1024 float4 slots
#pragma unroll
        for (int i = 0; i < 4; i++) {
            int slot = tid + i * 256;
            int kk = slot >> 5;
            int n4 = slot & 31;
            float4 val = *(const float4*)(W + (size_t)(k0 + kk) * 512 + bn + n4 * 4);
            unsigned* p = &Bs[kk * B_STRIDE + n4 * 4];
            p[0] = f2tf32(val.x);
            p[1] = f2tf32(val.y);
            p[2] = f2tf32(val.z);
            p[3] = f2tf32(val.w);
        }
        __syncthreads();
#pragma unroll
        for (int ks = 0; ks < 4; ks++) {
            const int k = ks * 8;
            unsigned afr[2][4];
#pragma unroll
            for (int mt = 0; mt < 2; mt++) {
                int r = wm + mt * 16 + g;
                afr[mt][0] = As[r * A_STRIDE + k + t];
                afr[mt][1] = As[(r + 8) * A_STRIDE + k + t];
                afr[mt][2] = As[r * A_STRIDE + k + t + 4];
                afr[mt][3] = As[(r + 8) * A_STRIDE + k + t + 4];
            }
            unsigned bfr[8][2];
#pragma unroll
            for (int nt = 0; nt < 8; nt++) {
                int n = wn + nt * 8 + g;
                bfr[nt][0] = Bs[(k + t) * B_STRIDE + n];
                bfr[nt][1] = Bs[(k + t + 4) * B_STRIDE + n];
            }
#pragma unroll
            for (int mt = 0; mt < 2; mt++)
#pragma unroll
                for (int nt = 0; nt < 8; nt++)
                    mma_tf32(acc[mt][nt], afr[mt], bfr[nt]);
        }
        __syncthreads();
    }

    // epilogue: d0,d1 -> (r, c),(r, c+1); d2,d3 -> (r+8, ...)
#pragma unroll
    for (int mt = 0; mt < 2; mt++) {
        int r0 = bm + wm + mt * 16 + g;
        int r1 = r0 + 8;
        float s0 = 1.0f, s1 = 1.0f;
        if (rowscale) {
            if (r0 < M) s0 = rowscale[r0];
            if (r1 < M) s1 = rowscale[r1];
        }
#pragma unroll
        for (int nt = 0; nt < 8; nt++) {
            int c = bn + wn + nt * 8 + t * 2;
            float b0 = 0.0f, b1 = 0.0f;
            if (bias) { b0 = bias[c]; b1 = bias[c + 1]; }
            if (r0 < M) {
                float2 v = make_float2(acc[mt][nt][0] * s0 + b0,
                                       acc[mt][nt][1] * s0 + b1);
                *(float2*)(C + (size_t)r0 * 512 + c) = v;
            }
            if (r1 < M) {
                float2 v = make_float2(acc[mt][nt][2] * s1 + b0,
                                       acc[mt][nt][3] * s1 + b1);
                *(float2*)(C + (size_t)r1 * 512 + c) = v;
            }
        }
    }
}

// ---------------- LayerNorm + ELU + write/accumulate into stacked slot -------
__global__ __launch_bounds__(128) void ln_elu_acc(
    const float* __restrict__ X, const float* __restrict__ rdi,
    const float* __restrict__ bias, const float* __restrict__ gamma,
    const float* __restrict__ beta, float* __restrict__ out, int accumulate) {
    int n = blockIdx.x;
    const float* x = X + (size_t)n * HH;
    float sc = rdi ? rdi[n] : 1.0f;
    float v[4];
    float sum = 0.0f;
#pragma unroll
    for (int i = 0; i < 4; i++) {
        int j = threadIdx.x + i * 128;
        v[i] = x[j] * sc + bias[j];
        sum += v[i];
    }
    sum = block_reduce_sum_128(sum);
    float u = sum * (1.0f / HH);
    float var = 0.0f;
#pragma unroll
    for (int i = 0; i < 4; i++) {
        float d = v[i] - u;
        var += d * d;
    }
    var = block_reduce_sum_128(var) * (1.0f / HH);
    float inv = rsqrtf(var + 1e-12f);
#pragma unroll
    for (int i = 0; i < 4; i++) {
        int j = threadIdx.x + i * 128;
        float y = gamma[j] * (v[i] - u) * inv + beta[j];
        y = (y > 0.0f) ? y : (expf(y) - 1.0f);
        float* o = out + (size_t)n * (RR * HH) + j;
        if (accumulate) *o += y; else *o = y;
    }
}

__global__ void init_ms(float* __restrict__ m, float* __restrict__ s) {
    int idx = blockIdx.x * blockDim.x + threadIdx.x;
    if (idx < NN * NHEADS) { m[idx] = -INFINITY; s[idx] = 0.0f; }
}

// ---------------- GraphConv scatter: agg[dst] += X[src] ----------------
__global__ void conv_scatter(const int* __restrict__ src, const int* __restrict__ dst,
                             const float* __restrict__ X, float* __restrict__ agg) {
    long long idx = (long long)blockIdx.x * blockDim.x + threadIdx.x;
    if (idx >= (long long)EE * HH) return;
    int e = (int)(idx >> 9);
    int j = (int)(idx & 511);
    atomicAdd(&agg[(size_t)dst[e] * HH + j], X[(size_t)src[e] * HH + j]);
}

// ---------------- GAT ----------------
__global__ void gat_el_er(const float* __restrict__ f, const float* __restrict__ al,
                          const float* __restrict__ ar, float* __restrict__ el,
                          float* __restrict__ er) {
    int idx = blockIdx.x * blockDim.x + threadIdx.x;
    if (idx >= NN * NHEADS) return;
    int n = idx >> 3;
    int hh = idx & 7;
    const float* fr = f + (size_t)n * HH + hh * DHH;
    const float* a1 = al + hh * DHH;
    const float* a2 = ar + hh * DHH;
    float s1 = 0.0f, s2 = 0.0f;
#pragma unroll 8
    for (int d = 0; d < DHH; d++) {
        float fv = fr[d];
        s1 += fv * a1[d];
        s2 += fv * a2[d];
    }
    el[idx] = s1;
    er[idx] = s2;
}

__global__ void gat_edge1(const int* __restrict__ src, const int* __restrict__ dst,
                          const float* __restrict__ el, const float* __restrict__ er,
                          float* __restrict__ e, float* __restrict__ m) {
    int idx = blockIdx.x * blockDim.x + threadIdx.x;
    if (idx >= EE * NHEADS) return;
    int ed = idx >> 3;
    int hh = idx & 7;
    float x = el[src[ed] * NHEADS + hh] + er[dst[ed] * NHEADS + hh];
    x = (x > 0.0f) ? x : 0.2f * x;
    e[idx] = x;
    atomicMaxFloat(&m[dst[ed] * NHEADS + hh], x);
}

__global__ void gat_edge2(const int* __restrict__ dst, float* __restrict__ e,
                          const float* __restrict__ m, float* __restrict__ s) {
    int idx = blockIdx.x * blockDim.x + threadIdx.x;
    if (idx >= EE * NHEADS) return;
    int ed = idx >> 3;
    int hh = idx & 7;
    float ex = expf(e[idx] - m[dst[ed] * NHEADS + hh]);
    e[idx] = ex;
    atomicAdd(&s[dst[ed] * NHEADS + hh], ex);
}

__global__ void gat_edge3(const int* __restrict__ src, const int* __restrict__ dst,
                          const float* __restrict__ e, const float* __restrict__ s,
                          const float* __restrict__ f, float* __restrict__ agg) {
    long long idx = (long long)blockIdx.x * blockDim.x + threadIdx.x;
    if (idx >= (long long)EE * HH) return;
    int ed = (int)(idx >> 9);
    int j = (int)(idx & 511);
    int hh = j >> 6;
    int dn = dst[ed];
    float sv = s[dn * NHEADS + hh];
    float alpha = e[ed * NHEADS + hh] / ((sv > 0.0f) ? sv : 1.0f);
    atomicAdd(&agg[(size_t)dn * HH + j], alpha * f[(size_t)src[ed] * HH + j]);
}

// ---------------- relation MHA (3 tokens) + mean over tokens ----------------
__global__ __launch_bounds__(256) void mha_mean(
    const float* __restrict__ q, const float* __restrict__ k,
    const float* __restrict__ v, float* __restrict__ out) {
    int n = blockIdx.x;
    int hd = threadIdx.x >> 5;
    int lane = threadIdx.x & 31;
    size_t base = (size_t)n * RR * HH + hd * DHH;
    float qa[RR], qb[RR], ka[RR], kb[RR], va[RR], vb[RR];
#pragma unroll
    for (int r = 0; r < RR; r++) {
        size_t off = base + (size_t)r * HH;
        qa[r] = q[off + lane];
        qb[r] = q[off + lane + 32];
        ka[r] = k[off + lane];
        kb[r] = k[off + lane + 32];
        va[r] = v[off + lane];
        vb[r] = v[off + lane + 32];
    }
    float sc[RR][RR];
#pragma unroll
    for (int r = 0; r < RR; r++)
#pragma unroll
        for (int t = 0; t < RR; t++) {
            float p = qa[r] * ka[t] + qb[r] * kb[t];
#pragma unroll
            for (int o = 16; o > 0; o >>= 1) p += __shfl_xor_sync(0xffffffffu, p, o);
            sc[r][t] = p * 0.125f;
        }
    float w0 = 0.0f, w1 = 0.0f, w2 = 0.0f;
#pragma unroll
    for (int r = 0; r < RR; r++) {
        float mx = fmaxf(sc[r][0], fmaxf(sc[r][1], sc[r][2]));
        float e0 = expf(sc[r][0] - mx);
        float e1 = expf(sc[r][1] - mx);
        float e2 = expf(sc[r][2] - mx);
        float inv = 1.0f / (e0 + e1 + e2);
        w0 += e0 * inv;
        w1 += e1 * inv;
        w2 += e2 * inv;
    }
    const float third = 1.0f / 3.0f;
    float oa = (w0 * va[0] + w1 * va[1] + w2 * va[2]) * third;
    float ob = (w0 * vb[0] + w1 * vb[1] + w2 * vb[2]) * third;
    out[(size_t)n * HH + hd * DHH + lane] = oa;
    out[(size_t)n * HH + hd * DHH + lane + 32] = ob;
}

// ---------------- classifier ----------------
__global__ void classify(const float* __restrict__ h, const float* __restrict__ W,
                         const float* __restrict__ b, float* __restrict__ out) {
    int idx = blockIdx.x * blockDim.x + threadIdx.x;
    if (idx >= NN * NCLSS) return;
    int n = idx / NCLSS;
    int c = idx % NCLSS;
    const float* hr = h + (size_t)n * HH;
    float sum = b[c];
#pragma unroll 8
    for (int j = 0; j < HH; j++) sum += hr[j] * W[j * NCLSS + c];
    out[idx] = sum;
}

// ---------------- launch ----------------
extern "C" void kernel_launch(void* const* d_in, const int* in_sizes, int n_in,
                              void* d_out, int out_size) {
    const float* feature = (const float*)d_in[0];
    const int* src = (const int*)d_in[1];
    const int* dst = (const int*)d_in[2];
    const float* Wc = (const float*)d_in[3];
    const float* bc = (const float*)d_in[4];
    const float* gc = (const float*)d_in[5];
    const float* betac = (const float*)d_in[6];
    const float* Wg = (const float*)d_in[7];
    const float* bg = (const float*)d_in[8];
    const float* al = (const float*)d_in[9];
    const float* ar = (const float*)d_in[10];
    const float* gg = (const float*)d_in[11];
    const float* betag = (const float*)d_in[12];
    const float* Ws = (const float*)d_in[13];
    const float* bs = (const float*)d_in[14];
    const float* gs = (const float*)d_in[15];
    const float* betas = (const float*)d_in[16];
    const float* Wq = (const float*)d_in[17];
    const float* bq = (const float*)d_in[18];
    const float* Wk = (const float*)d_in[19];
    const float* bk = (const float*)d_in[20];
    const float* Wv = (const float*)d_in[21];
    const float* bv = (const float*)d_in[22];
    const float* Wout = (const float*)d_in[23];
    const float* bout = (const float*)d_in[24];
    float* out = (float*)d_out;

    float *p_h, *p_tmp, *p_f, *p_agg, *p_stk, *p_q, *p_k, *p_v;
    float *p_rdo, *p_rdi, *p_el, *p_er, *p_m, *p_s, *p_e;
    cudaGetSymbolAddress((void**)&p_h, g_h);
    cudaGetSymbolAddress((void**)&p_tmp, g_tmp);
    cudaGetSymbolAddress((void**)&p_f, g_f);
    cudaGetSymbolAddress((void**)&p_agg, g_agg);
    cudaGetSymbolAddress((void**)&p_stk, g_stk);
    cudaGetSymbolAddress((void**)&p_q, g_q);
    cudaGetSymbolAddress((void**)&p_k, g_k);
    cudaGetSymbolAddress((void**)&p_v, g_v);
    cudaGetSymbolAddress((void**)&p_rdo, g_rdo);
    cudaGetSymbolAddress((void**)&p_rdi, g_rdi);
    cudaGetSymbolAddress((void**)&p_el, g_el);
    cudaGetSymbolAddress((void**)&p_er, g_er);
    cudaGetSymbolAddress((void**)&p_m, g_m);
    cudaGetSymbolAddress((void**)&p_s, g_s);
    cudaGetSymbolAddress((void**)&p_e, g_e);

    cudaMemcpyAsync(p_h, feature, (size_t)NN * HH * sizeof(float),
                    cudaMemcpyDeviceToDevice, 0);

    cudaMemsetAsync(p_rdo, 0, (size_t)RR * NN * sizeof(float), 0);
    cudaMemsetAsync(p_rdi, 0, (size_t)RR * NN * sizeof(float), 0);
    degree_count<<<(RR * EE + 255) / 256, 256>>>(src, dst, p_rdo, p_rdi);
    degree_finalize<<<(RR * NN + 255) / 256, 256>>>(p_rdo, RR * NN);
    degree_finalize<<<(RR * NN + 255) / 256, 256>>>(p_rdi, RR * NN);

    const dim3 gemm_grid_n(4, (NN + 127) / 128);
    const dim3 gemm_grid_nr(4, (NN * RR + 127) / 128);
    const int eh_blocks = (int)(((long long)EE * HH + 255) / 256);
    const int ehd_blocks = (EE * NHEADS + 255) / 256;
    const int nhd_blocks = (NN * NHEADS + 255) / 256;

    for (int l = 0; l < LL; l++) {
        for (int r = 0; r < RR; r++) {
            const size_t lr = (size_t)(l * RR + r);
            const float* Wc_lr = Wc + lr * HH * HH;
            const float* Wg_lr = Wg + lr * HH * HH;
            const float* Ws_lr = Ws + lr * HH * HH;
            const float* bc_lr = bc + lr * HH;
            const float* gc_lr = gc + lr * HH;
            const float* betac_lr = betac + lr * HH;
            const float* bg_lr = bg + lr * HH;
            const float* gg_lr = gg + lr * HH;
            const float* betag_lr = betag + lr * HH;
            const float* bs_lr = bs + lr * HH;
            const float* gs_lr = gs + lr * HH;
            const float* betas_lr = betas + lr * HH;
            const float* al_lr = al + lr * NHEADS * DHH;
            const float* ar_lr = ar + lr * NHEADS * DHH;
            const int* src_r = src + (size_t)r * EE;
            const int* dst_r = dst + (size_t)r * EE;

            // ---- GraphConv ----
            tf32gemm512<<<gemm_grid_n, 256>>>(p_h, Wc_lr, p_tmp, NN,
                                              p_rdo + (size_t)r * NN, nullptr);
            cudaMemsetAsync(p_agg, 0, (size_t)NN * HH * sizeof(float), 0);
            conv_scatter<<<eh_blocks, 256>>>(src_r, dst_r, p_tmp, p_agg);
            ln_elu_acc<<<NN, 128>>>(p_agg, p_rdi + (size_t)r * NN, bc_lr, gc_lr,
                                    betac_lr, p_stk + (size_t)r * HH, 0);

            // ---- GATConv ----
            tf32gemm512<<<gemm_grid_n, 256>>>(p_h, Wg_lr, p_f, NN, nullptr, nullptr);
            gat_el_er<<<nhd_blocks, 256>>>(p_f, al_lr, ar_lr, p_el, p_er);
            init_ms<<<nhd_blocks, 256>>>(p_m, p_s);
            gat_edge1<<<ehd_blocks, 256>>>(src_r, dst_r, p_el, p_er, p_e, p_m);
            gat_edge2<<<ehd_blocks, 256>>>(dst_r, p_e, p_m, p_s);
            cudaMemsetAsync(p_agg, 0, (size_t)NN * HH * sizeof(float), 0);
            gat_edge3<<<eh_blocks, 256>>>(src_r, dst_r, p_e, p_s, p_f, p_agg);
            ln_elu_acc<<<NN, 128>>>(p_agg, nullptr, bg_lr, gg_lr, betag_lr,
                                    p_stk + (size_t)r * HH, 1);

            // ---- skip ----
            tf32gemm512<<<gemm_grid_n, 256>>>(p_h, Ws_lr, p_tmp, NN, nullptr, nullptr);
            ln_elu_acc<<<NN, 128>>>(p_tmp, nullptr, bs_lr, gs_lr, betas_lr,
                                    p_stk + (size_t)r * HH, 1);
        }

        // ---- relation MHA ----
        const float* Wq_l = Wq + (size_t)l * HH * HH;
        const float* Wk_l = Wk + (size_t)l * HH * HH;
        const float* Wv_l = Wv + (size_t)l * HH * HH;
        tf32gemm512<<<gemm_grid_nr, 256>>>(p_stk, Wq_l, p_q, NN * RR, nullptr,
                                           bq + (size_t)l * HH);
        tf32gemm512<<<gemm_grid_nr, 256>>>(p_stk, Wk_l, p_k, NN * RR, nullptr,
                                           bk + (size_t)l * HH);
        tf32gemm512<<<gemm_grid_nr, 256>>>(p_stk, Wv_l, p_v, NN * RR, nullptr,
                                           bv + (size_t)l * HH);
        mha_mean<<<NN, 256>>>(p_q, p_k, p_v, p_h);
    }

    classify<<<(NN * NCLSS + 255) / 256, 256>>>(p_h, Wout, bout, out);
}

// round 5
// speedup vs baseline: 2.6855x; 1.4200x over previous
#include <cuda_runtime.h>
#include <math.h>

#define NN 50000
#define EE 150000
#define RR 3
#define LL 2
#define HH 512
#define NHEADS 8
#define DHH 64
#define NCLSS 23

// ---------------- scratch (device globals; no allocs allowed) ----------------
__device__ float g_h[(size_t)NN * HH];
__device__ float g_tmp[(size_t)NN * HH];
__device__ float g_f[(size_t)NN * HH];
__device__ float g_stk[(size_t)NN * RR * HH];
__device__ float g_q[(size_t)NN * RR * HH];
__device__ float g_k[(size_t)NN * RR * HH];
__device__ float g_v[(size_t)NN * RR * HH];
__device__ float g_rdo[(size_t)RR * NN];
__device__ float g_rdi[(size_t)RR * NN];
__device__ float g_el[(size_t)NN * NHEADS];
__device__ float g_er[(size_t)NN * NHEADS];
__device__ float g_m[(size_t)NN * NHEADS];
__device__ float g_s[(size_t)NN * NHEADS];
__device__ float g_e[(size_t)EE * NHEADS];
// CSR (dst-indexed) per relation
__device__ int g_cnt[(size_t)RR * NN];
__device__ int g_cur[(size_t)RR * NN];
__device__ int g_off[(size_t)RR * (NN + 1)];
__device__ int g_eid[(size_t)RR * EE];

// ---------------- helpers ----------------
__device__ __forceinline__ void atomicMaxFloat(float* addr, float val) {
    if (val >= 0.0f) {
        atomicMax((int*)addr, __float_as_int(val));
    } else {
        atomicMin((unsigned int*)addr, (unsigned int)__float_as_int(val));
    }
}

__device__ __forceinline__ float block_reduce_sum_128(float val) {
    __shared__ float sh[32];
    __syncthreads();
    int lane = threadIdx.x & 31;
    int wid = threadIdx.x >> 5;
#pragma unroll
    for (int o = 16; o > 0; o >>= 1) val += __shfl_xor_sync(0xffffffffu, val, o);
    if (lane == 0) sh[wid] = val;
    __syncthreads();
    if (wid == 0) {
        float v = (lane < (blockDim.x >> 5)) ? sh[lane] : 0.0f;
#pragma unroll
        for (int o = 16; o > 0; o >>= 1) v += __shfl_xor_sync(0xffffffffu, v, o);
        if (lane == 0) sh[0] = v;
    }
    __syncthreads();
    return sh[0];
}

__device__ __forceinline__ unsigned f2tf32(float x) {
    unsigned r;
    asm("cvt.rna.tf32.f32 %0, %1;" : "=r"(r) : "f"(x));
    return r;
}

__device__ __forceinline__ void mma_tf32(float* d, const unsigned* a, const unsigned* b) {
    asm volatile(
        "mma.sync.aligned.m16n8k8.row.col.f32.tf32.tf32.f32 "
        "{%0,%1,%2,%3}, {%4,%5,%6,%7}, {%8,%9}, {%0,%1,%2,%3};"
        : "+f"(d[0]), "+f"(d[1]), "+f"(d[2]), "+f"(d[3])
        : "r"(a[0]), "r"(a[1]), "r"(a[2]), "r"(a[3]), "r"(b[0]), "r"(b[1]));
}

// ---------------- degree + CSR build ----------------
__global__ void degree_count(const int* __restrict__ src, const int* __restrict__ dst,
                             float* __restrict__ rdo, float* __restrict__ rdi,
                             int* __restrict__ cnt) {
    int idx = blockIdx.x * blockDim.x + threadIdx.x;
    if (idx >= RR * EE) return;
    int r = idx / EE;
    int d = dst[idx];
    atomicAdd(&rdo[(size_t)r * NN + src[idx]], 1.0f);
    atomicAdd(&rdi[(size_t)r * NN + d], 1.0f);
    atomicAdd(&cnt[(size_t)r * NN + d], 1);
}

__global__ void degree_finalize(float* __restrict__ p, int n) {
    int idx = blockIdx.x * blockDim.x + threadIdx.x;
    if (idx < n) p[idx] = rsqrtf(fmaxf(p[idx], 1.0f));
}

// one block (1024 thr) per relation: exclusive prefix sum of counts
__global__ __launch_bounds__(1024) void scan_offsets(const int* __restrict__ cnt,
                                                     int* __restrict__ off) {
    int r = blockIdx.x;
    const int* c = cnt + (size_t)r * NN;
    int* o = off + (size_t)r * (NN + 1);
    __shared__ int warp_sums[32];
    __shared__ int s_carry;
    if (threadIdx.x == 0) s_carry = 0;
    __syncthreads();
    int lane = threadIdx.x & 31;
    int w = threadIdx.x >> 5;
    for (int base = 0; base < NN; base += 1024) {
        int idx = base + threadIdx.x;
        int val = (idx < NN) ? c[idx] : 0;
        int x = val;
#pragma unroll
        for (int s = 1; s < 32; s <<= 1) {
            int y = __shfl_up_sync(0xffffffffu, x, s);
            if (lane >= s) x += y;
        }
        if (lane == 31) warp_sums[w] = x;
        __syncthreads();
        if (w == 0) {
            int y = warp_sums[lane];
#pragma unroll
            for (int s = 1; s < 32; s <<= 1) {
                int z = __shfl_up_sync(0xffffffffu, y, s);
                if (lane >= s) y += z;
            }
            warp_sums[lane] = y;
        }
        __syncthreads();
        int excl = x - val + ((w > 0) ? warp_sums[w - 1] : 0) + s_carry;
        if (idx < NN) o[idx] = excl;
        int chunk_total = warp_sums[31];
        __syncthreads();
        if (threadIdx.x == 0) s_carry += chunk_total;
        __syncthreads();
    }
    if (threadIdx.x == 0) o[NN] = s_carry;
}

__global__ void build_adj(const int* __restrict__ dst, const int* __restrict__ off,
                          int* __restrict__ cur, int* __restrict__ eid) {
    int idx = blockIdx.x * blockDim.x + threadIdx.x;
    if (idx >= RR * EE) return;
    int r = idx / EE;
    int e = idx - r * EE;
    int d = dst[idx];
    int pos = atomicAdd(&cur[(size_t)r * NN + d], 1);
    eid[(size_t)r * EE + off[(size_t)r * (NN + 1) + d] + pos] = e;
}

// ---------------- TF32 tensor-core GEMM -------------------------------------
#define A_STRIDE 36
#define B_STRIDE 136
__global__ __launch_bounds__(256) void tf32gemm512(
    const float* __restrict__ A, const float* __restrict__ W,
    float* __restrict__ C, int M,
    const float* __restrict__ rowscale, const float* __restrict__ bias) {
    __shared__ unsigned As[128 * A_STRIDE];
    __shared__ unsigned Bs[32 * B_STRIDE];

    const int bm = blockIdx.y * 128;
    const int bn = blockIdx.x * 128;
    const int tid = threadIdx.x;
    const int warp = tid >> 5;
    const int lane = tid & 31;
    const int g = lane >> 2;
    const int t = lane & 3;
    const int wm = (warp >> 1) * 32;
    const int wn = (warp & 1) * 64;

    float acc[2][8][4];
#pragma unroll
    for (int i = 0; i < 2; i++)
#pragma unroll
        for (int j = 0; j < 8; j++)
#pragma unroll
            for (int q = 0; q < 4; q++) acc[i][j][q] = 0.0f;

    for (int k0 = 0; k0 < 512; k0 += 32) {
#pragma unroll
        for (int i = 0; i < 4; i++) {
            int slot = tid + i * 256;
            int row = slot >> 3;
            int c4 = slot & 7;
            float4 val = make_float4(0.f, 0.f, 0.f, 0.f);
            int gr = bm + row;
            if (gr < M) val = *(const float4*)(A + (size_t)gr * 512 + k0 + c4 * 4);
            unsigned* p = &As[row * A_STRIDE + c4 * 4];
            p[0] = f2tf32(val.x);
            p[1] = f2tf32(val.y);
            p[2] = f2tf32(val.z);
            p[3] = f2tf32(val.w);
        }
#pragma unroll
        for (int i = 0; i < 4; i++) {
            int slot = tid + i * 256;
            int kk = slot >> 5;
            int n4 = slot & 31;
            float4 val = *(const float4*)(W + (size_t)(k0 + kk) * 512 + bn + n4 * 4);
            unsigned* p = &Bs[kk * B_STRIDE + n4 * 4];
            p[0] = f2tf32(val.x);
            p[1] = f2tf32(val.y);
            p[2] = f2tf32(val.z);
            p[3] = f2tf32(val.w);
        }
        __syncthreads();
#pragma unroll
        for (int ks = 0; ks < 4; ks++) {
            const int k = ks * 8;
            unsigned afr[2][4];
#pragma unroll
            for (int mt = 0; mt < 2; mt++) {
                int r = wm + mt * 16 + g;
                afr[mt][0] = As[r * A_STRIDE + k + t];
                afr[mt][1] = As[(r + 8) * A_STRIDE + k + t];
                afr[mt][2] = As[r * A_STRIDE + k + t + 4];
                afr[mt][3] = As[(r + 8) * A_STRIDE + k + t + 4];
            }
            unsigned bfr[8][2];
#pragma unroll
            for (int nt = 0; nt < 8; nt++) {
                int n = wn + nt * 8 + g;
                bfr[nt][0] = Bs[(k + t) * B_STRIDE + n];
                bfr[nt][1] = Bs[(k + t + 4) * B_STRIDE + n];
            }
#pragma unroll
            for (int mt = 0; mt < 2; mt++)
#pragma unroll
                for (int nt = 0; nt < 8; nt++)
                    mma_tf32(acc[mt][nt], afr[mt], bfr[nt]);
        }
        __syncthreads();
    }

#pragma unroll
    for (int mt = 0; mt < 2; mt++) {
        int r0 = bm + wm + mt * 16 + g;
        int r1 = r0 + 8;
        float s0 = 1.0f, s1 = 1.0f;
        if (rowscale) {
            if (r0 < M) s0 = rowscale[r0];
            if (r1 < M) s1 = rowscale[r1];
        }
#pragma unroll
        for (int nt = 0; nt < 8; nt++) {
            int c = bn + wn + nt * 8 + t * 2;
            float b0 = 0.0f, b1 = 0.0f;
            if (bias) { b0 = bias[c]; b1 = bias[c + 1]; }
            if (r0 < M) {
                float2 v = make_float2(acc[mt][nt][0] * s0 + b0,
                                       acc[mt][nt][1] * s0 + b1);
                *(float2*)(C + (size_t)r0 * 512 + c) = v;
            }
            if (r1 < M) {
                float2 v = make_float2(acc[mt][nt][2] * s1 + b0,
                                       acc[mt][nt][3] * s1 + b1);
                *(float2*)(C + (size_t)r1 * 512 + c) = v;
            }
        }
    }
}

// ---------------- LN core (thread owns cols 4t..4t+3) ----------------
__device__ __forceinline__ void ln_elu_store4(
    float4 v, const float* __restrict__ gamma, const float* __restrict__ beta,
    float* __restrict__ optr, int accumulate) {
    int t = threadIdx.x;
    float sum = v.x + v.y + v.z + v.w;
    sum = block_reduce_sum_128(sum);
    float u = sum * (1.0f / HH);
    float dx = v.x - u, dy = v.y - u, dz = v.z - u, dw = v.w - u;
    float var = dx * dx + dy * dy + dz * dz + dw * dw;
    var = block_reduce_sum_128(var) * (1.0f / HH);
    float inv = rsqrtf(var + 1e-12f);
    float4 ga = ((const float4*)gamma)[t];
    float4 be = ((const float4*)beta)[t];
    float y0 = ga.x * dx * inv + be.x;
    float y1 = ga.y * dy * inv + be.y;
    float y2 = ga.z * dz * inv + be.z;
    float y3 = ga.w * dw * inv + be.w;
    y0 = (y0 > 0.0f) ? y0 : (expf(y0) - 1.0f);
    y1 = (y1 > 0.0f) ? y1 : (expf(y1) - 1.0f);
    y2 = (y2 > 0.0f) ? y2 : (expf(y2) - 1.0f);
    y3 = (y3 > 0.0f) ? y3 : (expf(y3) - 1.0f);
    float4* o = (float4*)(optr + 4 * t);
    if (accumulate) {
        float4 old = *o;
        y0 += old.x; y1 += old.y; y2 += old.z; y3 += old.w;
    }
    *o = make_float4(y0, y1, y2, y3);
}

// ---------------- fused conv gather + LN + ELU ----------------
__global__ __launch_bounds__(128) void conv_gather_ln(
    const int* __restrict__ eid, const int* __restrict__ off,
    const int* __restrict__ src, const float* __restrict__ X,
    const float* __restrict__ rdi, const float* __restrict__ bias,
    const float* __restrict__ gamma, const float* __restrict__ beta,
    float* __restrict__ out) {
    int n = blockIdx.x;
    int p0 = off[n], p1 = off[n + 1];
    int t = threadIdx.x;
    float4 acc = make_float4(0.f, 0.f, 0.f, 0.f);
    for (int p = p0; p < p1; p++) {
        int sn = src[eid[p]];
        float4 rv = ((const float4*)(X + (size_t)sn * HH))[t];
        acc.x += rv.x; acc.y += rv.y; acc.z += rv.z; acc.w += rv.w;
    }
    float sc = rdi[n];
    float4 bb = ((const float4*)bias)[t];
    float4 v = make_float4(acc.x * sc + bb.x, acc.y * sc + bb.y,
                           acc.z * sc + bb.z, acc.w * sc + bb.w);
    ln_elu_store4(v, gamma, beta, out + (size_t)n * (RR * HH), 0);
}

// ---------------- fused GAT gather + LN + ELU (accumulate) ----------------
__global__ __launch_bounds__(128) void gat_gather_ln(
    const int* __restrict__ eid, const int* __restrict__ off,
    const int* __restrict__ src, const float* __restrict__ f,
    const float* __restrict__ e_arr, const float* __restrict__ s_arr,
    const float* __restrict__ bias, const float* __restrict__ gamma,
    const float* __restrict__ beta, float* __restrict__ out) {
    int n = blockIdx.x;
    int p0 = off[n], p1 = off[n + 1];
    int t = threadIdx.x;
    int h = t >> 4;  // cols 4t..4t+3 share head (4t)>>6
    float sv = s_arr[n * NHEADS + h];
    float invs = (sv > 0.0f) ? (1.0f / sv) : 1.0f;
    float4 acc = make_float4(0.f, 0.f, 0.f, 0.f);
    for (int p = p0; p < p1; p++) {
        int e = eid[p];
        int sn = src[e];
        float a = e_arr[(size_t)e * NHEADS + h] * invs;
        float4 rv = ((const float4*)(f + (size_t)sn * HH))[t];
        acc.x += a * rv.x; acc.y += a * rv.y;
        acc.z += a * rv.z; acc.w += a * rv.w;
    }
    float4 bb = ((const float4*)bias)[t];
    float4 v = make_float4(acc.x + bb.x, acc.y + bb.y, acc.z + bb.z, acc.w + bb.w);
    ln_elu_store4(v, gamma, beta, out + (size_t)n * (RR * HH), 1);
}

// ---------------- skip LN (reads dense X row) ----------------
__global__ __launch_bounds__(128) void skip_ln(
    const float* __restrict__ X, const float* __restrict__ bias,
    const float* __restrict__ gamma, const float* __restrict__ beta,
    float* __restrict__ out) {
    int n = blockIdx.x;
    int t = threadIdx.x;
    float4 x = ((const float4*)(X + (size_t)n * HH))[t];
    float4 bb = ((const float4*)bias)[t];
    float4 v = make_float4(x.x + bb.x, x.y + bb.y, x.z + bb.z, x.w + bb.w);
    ln_elu_store4(v, gamma, beta, out + (size_t)n * (RR * HH), 1);
}

__global__ void init_ms(float* __restrict__ m, float* __restrict__ s) {
    int idx = blockIdx.x * blockDim.x + threadIdx.x;
    if (idx < NN * NHEADS) { m[idx] = -INFINITY; s[idx] = 0.0f; }
}

// ---------------- GAT edge-stat kernels ----------------
__global__ void gat_el_er(const float* __restrict__ f, const float* __restrict__ al,
                          const float* __restrict__ ar, float* __restrict__ el,
                          float* __restrict__ er) {
    int idx = blockIdx.x * blockDim.x + threadIdx.x;
    if (idx >= NN * NHEADS) return;
    int n = idx >> 3;
    int hh = idx & 7;
    const float* fr = f + (size_t)n * HH + hh * DHH;
    const float* a1 = al + hh * DHH;
    const float* a2 = ar + hh * DHH;
    float s1 = 0.0f, s2 = 0.0f;
#pragma unroll 8
    for (int d = 0; d < DHH; d++) {
        float fv = fr[d];
        s1 += fv * a1[d];
        s2 += fv * a2[d];
    }
    el[idx] = s1;
    er[idx] = s2;
}

__global__ void gat_edge1(const int* __restrict__ src, const int* __restrict__ dst,
                          const float* __restrict__ el, const float* __restrict__ er,
                          float* __restrict__ e, float* __restrict__ m) {
    int idx = blockIdx.x * blockDim.x + threadIdx.x;
    if (idx >= EE * NHEADS) return;
    int ed = idx >> 3;
    int hh = idx & 7;
    float x = el[src[ed] * NHEADS + hh] + er[dst[ed] * NHEADS + hh];
    x = (x > 0.0f) ? x : 0.2f * x;
    e[idx] = x;
    atomicMaxFloat(&m[dst[ed] * NHEADS + hh], x);
}

__global__ void gat_edge2(const int* __restrict__ dst, float* __restrict__ e,
                          const float* __restrict__ m, float* __restrict__ s) {
    int idx = blockIdx.x * blockDim.x + threadIdx.x;
    if (idx >= EE * NHEADS) return;
    int ed = idx >> 3;
    int hh = idx & 7;
    float ex = expf(e[idx] - m[dst[ed] * NHEADS + hh]);
    e[idx] = ex;
    atomicAdd(&s[dst[ed] * NHEADS + hh], ex);
}

// ---------------- relation MHA (3 tokens) + mean over tokens ----------------
__global__ __launch_bounds__(256) void mha_mean(
    const float* __restrict__ q, const float* __restrict__ k,
    const float* __restrict__ v, float* __restrict__ out) {
    int n = blockIdx.x;
    int hd = threadIdx.x >> 5;
    int lane = threadIdx.x & 31;
    size_t base = (size_t)n * RR * HH + hd * DHH;
    float qa[RR], qb[RR], ka[RR], kb[RR], va[RR], vb[RR];
#pragma unroll
    for (int r = 0; r < RR; r++) {
        size_t off = base + (size_t)r * HH;
        qa[r] = q[off + lane];
        qb[r] = q[off + lane + 32];
        ka[r] = k[off + lane];
        kb[r] = k[off + lane + 32];
        va[r] = v[off + lane];
        vb[r] = v[off + lane + 32];
    }
    float sc[RR][RR];
#pragma unroll
    for (int r = 0; r < RR; r++)
#pragma unroll
        for (int t = 0; t < RR; t++) {
            float p = qa[r] * ka[t] + qb[r] * kb[t];
#pragma unroll
            for (int o = 16; o > 0; o >>= 1) p += __shfl_xor_sync(0xffffffffu, p, o);
            sc[r][t] = p * 0.125f;
        }
    float w0 = 0.0f, w1 = 0.0f, w2 = 0.0f;
#pragma unroll
    for (int r = 0; r < RR; r++) {
        float mx = fmaxf(sc[r][0], fmaxf(sc[r][1], sc[r][2]));
        float e0 = expf(sc[r][0] - mx);
        float e1 = expf(sc[r][1] - mx);
        float e2 = expf(sc[r][2] - mx);
        float inv = 1.0f / (e0 + e1 + e2);
        w0 += e0 * inv;
        w1 += e1 * inv;
        w2 += e2 * inv;
    }
    const float third = 1.0f / 3.0f;
    float oa = (w0 * va[0] + w1 * va[1] + w2 * va[2]) * third;
    float ob = (w0 * vb[0] + w1 * vb[1] + w2 * vb[2]) * third;
    out[(size_t)n * HH + hd * DHH + lane] = oa;
    out[(size_t)n * HH + hd * DHH + lane + 32] = ob;
}

// ---------------- classifier ----------------
__global__ void classify(const float* __restrict__ h, const float* __restrict__ W,
                         const float* __restrict__ b, float* __restrict__ out) {
    int idx = blockIdx.x * blockDim.x + threadIdx.x;
    if (idx >= NN * NCLSS) return;
    int n = idx / NCLSS;
    int c = idx % NCLSS;
    const float* hr = h + (size_t)n * HH;
    float sum = b[c];
#pragma unroll 8
    for (int j = 0; j < HH; j++) sum += hr[j] * W[j * NCLSS + c];
    out[idx] = sum;
}

// ---------------- launch ----------------
extern "C" void kernel_launch(void* const* d_in, const int* in_sizes, int n_in,
                              void* d_out, int out_size) {
    const float* feature = (const float*)d_in[0];
    const int* src = (const int*)d_in[1];
    const int* dst = (const int*)d_in[2];
    const float* Wc = (const float*)d_in[3];
    const float* bc = (const float*)d_in[4];
    const float* gc = (const float*)d_in[5];
    const float* betac = (const float*)d_in[6];
    const float* Wg = (const float*)d_in[7];
    const float* bg = (const float*)d_in[8];
    const float* al = (const float*)d_in[9];
    const float* ar = (const float*)d_in[10];
    const float* gg = (const float*)d_in[11];
    const float* betag = (const float*)d_in[12];
    const float* Ws = (const float*)d_in[13];
    const float* bs = (const float*)d_in[14];
    const float* gs = (const float*)d_in[15];
    const float* betas = (const float*)d_in[16];
    const float* Wq = (const float*)d_in[17];
    const float* bq = (const float*)d_in[18];
    const float* Wk = (const float*)d_in[19];
    const float* bk = (const float*)d_in[20];
    const float* Wv = (const float*)d_in[21];
    const float* bv = (const float*)d_in[22];
    const float* Wout = (const float*)d_in[23];
    const float* bout = (const float*)d_in[24];
    float* out = (float*)d_out;

    float *p_h, *p_tmp, *p_f, *p_stk, *p_q, *p_k, *p_v;
    float *p_rdo, *p_rdi, *p_el, *p_er, *p_m, *p_s, *p_e;
    int *p_cnt, *p_cur, *p_off, *p_eid;
    cudaGetSymbolAddress((void**)&p_h, g_h);
    cudaGetSymbolAddress((void**)&p_tmp, g_tmp);
    cudaGetSymbolAddress((void**)&p_f, g_f);
    cudaGetSymbolAddress((void**)&p_stk, g_stk);
    cudaGetSymbolAddress((void**)&p_q, g_q);
    cudaGetSymbolAddress((void**)&p_k, g_k);
    cudaGetSymbolAddress((void**)&p_v, g_v);
    cudaGetSymbolAddress((void**)&p_rdo, g_rdo);
    cudaGetSymbolAddress((void**)&p_rdi, g_rdi);
    cudaGetSymbolAddress((void**)&p_el, g_el);
    cudaGetSymbolAddress((void**)&p_er, g_er);
    cudaGetSymbolAddress((void**)&p_m, g_m);
    cudaGetSymbolAddress((void**)&p_s, g_s);
    cudaGetSymbolAddress((void**)&p_e, g_e);
    cudaGetSymbolAddress((void**)&p_cnt, g_cnt);
    cudaGetSymbolAddress((void**)&p_cur, g_cur);
    cudaGetSymbolAddress((void**)&p_off, g_off);
    cudaGetSymbolAddress((void**)&p_eid, g_eid);

    cudaMemcpyAsync(p_h, feature, (size_t)NN * HH * sizeof(float),
                    cudaMemcpyDeviceToDevice, 0);

    // degrees + CSR (same graph for both layers)
    cudaMemsetAsync(p_rdo, 0, (size_t)RR * NN * sizeof(float), 0);
    cudaMemsetAsync(p_rdi, 0, (size_t)RR * NN * sizeof(float), 0);
    cudaMemsetAsync(p_cnt, 0, (size_t)RR * NN * sizeof(int), 0);
    cudaMemsetAsync(p_cur, 0, (size_t)RR * NN * sizeof(int), 0);
    degree_count<<<(RR * EE + 255) / 256, 256>>>(src, dst, p_rdo, p_rdi, p_cnt);
    degree_finalize<<<(RR * NN + 255) / 256, 256>>>(p_rdo, RR * NN);
    degree_finalize<<<(RR * NN + 255) / 256, 256>>>(p_rdi, RR * NN);
    scan_offsets<<<RR, 1024>>>(p_cnt, p_off);
    build_adj<<<(RR * EE + 255) / 256, 256>>>(dst, p_off, p_cur, p_eid);

    const dim3 gemm_grid_n(4, (NN + 127) / 128);
    const dim3 gemm_grid_nr(4, (NN * RR + 127) / 128);
    const int ehd_blocks = (EE * NHEADS + 255) / 256;
    const int nhd_blocks = (NN * NHEADS + 255) / 256;

    for (int l = 0; l < LL; l++) {
        for (int r = 0; r < RR; r++) {
            const size_t lr = (size_t)(l * RR + r);
            const float* Wc_lr = Wc + lr * HH * HH;
            const float* Wg_lr = Wg + lr * HH * HH;
            const float* Ws_lr = Ws + lr * HH * HH;
            const float* bc_lr = bc + lr * HH;
            const float* gc_lr = gc + lr * HH;
            const float* betac_lr = betac + lr * HH;
            const float* bg_lr = bg + lr * HH;
            const float* gg_lr = gg + lr * HH;
            const float* betag_lr = betag + lr * HH;
            const float* bs_lr = bs + lr * HH;
            const float* gs_lr = gs + lr * HH;
            const float* betas_lr = betas + lr * HH;
            const float* al_lr = al + lr * NHEADS * DHH;
            const float* ar_lr = ar + lr * NHEADS * DHH;
            const int* src_r = src + (size_t)r * EE;
            const int* dst_r = dst + (size_t)r * EE;
            const int* eid_r = p_eid + (size_t)r * EE;
            const int* off_r = p_off + (size_t)r * (NN + 1);

            // ---- GraphConv: GEMM(*deg_out^-1/2) -> CSR gather + LN + ELU ----
            tf32gemm512<<<gemm_grid_n, 256>>>(p_h, Wc_lr, p_tmp, NN,
                                              p_rdo + (size_t)r * NN, nullptr);
            conv_gather_ln<<<NN, 128>>>(eid_r, off_r, src_r, p_tmp,
                                        p_rdi + (size_t)r * NN, bc_lr, gc_lr,
                                        betac_lr, p_stk + (size_t)r * HH);

            // ---- GATConv ----
            tf32gemm512<<<gemm_grid_n, 256>>>(p_h, Wg_lr, p_f, NN, nullptr, nullptr);
            gat_el_er<<<nhd_blocks, 256>>>(p_f, al_lr, ar_lr, p_el, p_er);
            init_ms<<<nhd_blocks, 256>>>(p_m, p_s);
            gat_edge1<<<ehd_blocks, 256>>>(src_r, dst_r, p_el, p_er, p_e, p_m);
            gat_edge2<<<ehd_blocks, 256>>>(dst_r, p_e, p_m, p_s);
            gat_gather_ln<<<NN, 128>>>(eid_r, off_r, src_r, p_f, p_e, p_s,
                                       bg_lr, gg_lr, betag_lr,
                                       p_stk + (size_t)r * HH);

            // ---- skip ----
            tf32gemm512<<<gemm_grid_n, 256>>>(p_h, Ws_lr, p_tmp, NN, nullptr, nullptr);
            skip_ln<<<NN, 128>>>(p_tmp, bs_lr, gs_lr, betas_lr,
                                 p_stk + (size_t)r * HH);
        }

        // ---- relation MHA ----
        const float* Wq_l = Wq + (size_t)l * HH * HH;
        const float* Wk_l = Wk + (size_t)l * HH * HH;
        const float* Wv_l = Wv + (size_t)l * HH * HH;
        tf32gemm512<<<gemm_grid_nr, 256>>>(p_stk, Wq_l, p_q, NN * RR, nullptr,
                                           bq + (size_t)l * HH);
        tf32gemm512<<<gemm_grid_nr, 256>>>(p_stk, Wk_l, p_k, NN * RR, nullptr,
                                           bk + (size_t)l * HH);
        tf32gemm512<<<gemm_grid_nr, 256>>>(p_stk, Wv_l, p_v, NN * RR, nullptr,
                                           bv + (size_t)l * HH);
        mha_mean<<<NN, 256>>>(p_q, p_k, p_v, p_h);
    }

    classify<<<(NN * NCLSS + 255) / 256, 256>>>(p_h, Wout, bout, out);
}

// round 6
// speedup vs baseline: 3.1029x; 1.1554x over previous
#include <cuda_runtime.h>
#include <math.h>

#define NN 50000
#define EE 150000
#define RR 3
#define LL 2
#define HH 512
#define NHEADS 8
#define DHH 64
#define NCLSS 23

// ---------------- scratch (device globals; no allocs allowed) ----------------
__device__ float g_h[(size_t)NN * HH];
__device__ unsigned g_h32[(size_t)NN * HH];
__device__ float g_tmp[(size_t)NN * HH];
__device__ float g_tmp2[(size_t)NN * HH];
__device__ float g_f[(size_t)NN * HH];
__device__ float g_stk[(size_t)NN * RR * HH];
__device__ unsigned g_stk32[(size_t)NN * RR * HH];
__device__ float g_q[(size_t)NN * RR * HH];
__device__ float g_k[(size_t)NN * RR * HH];
__device__ float g_v[(size_t)NN * RR * HH];
__device__ unsigned g_w32[(size_t)24 * HH * HH];  // Wc(6) Wg(6) Ws(6) Wq(2) Wk(2) Wv(2)
__device__ float g_rdo[(size_t)RR * NN];
__device__ float g_rdi[(size_t)RR * NN];
__device__ float g_el[(size_t)NN * NHEADS];
__device__ float g_er[(size_t)NN * NHEADS];
__device__ float g_m[(size_t)NN * NHEADS];
__device__ float g_s[(size_t)NN * NHEADS];
__device__ float g_e[(size_t)EE * NHEADS];
// CSR (dst-indexed) per relation
__device__ int g_cnt[(size_t)RR * NN];
__device__ int g_cur[(size_t)RR * NN];
__device__ int g_off[(size_t)RR * (NN + 1)];
__device__ int g_eid[(size_t)RR * EE];

// ---------------- helpers ----------------
__device__ __forceinline__ void atomicMaxFloat(float* addr, float val) {
    if (val >= 0.0f) {
        atomicMax((int*)addr, __float_as_int(val));
    } else {
        atomicMin((unsigned int*)addr, (unsigned int)__float_as_int(val));
    }
}

__device__ __forceinline__ float block_reduce_sum_128(float val) {
    __shared__ float sh[32];
    __syncthreads();
    int lane = threadIdx.x & 31;
    int wid = threadIdx.x >> 5;
#pragma unroll
    for (int o = 16; o > 0; o >>= 1) val += __shfl_xor_sync(0xffffffffu, val, o);
    if (lane == 0) sh[wid] = val;
    __syncthreads();
    if (wid == 0) {
        float v = (lane < (blockDim.x >> 5)) ? sh[lane] : 0.0f;
#pragma unroll
        for (int o = 16; o > 0; o >>= 1) v += __shfl_xor_sync(0xffffffffu, v, o);
        if (lane == 0) sh[0] = v;
    }
    __syncthreads();
    return sh[0];
}

__device__ __forceinline__ unsigned f2tf32(float x) {
    unsigned r;
    asm("cvt.rna.tf32.f32 %0, %1;" : "=r"(r) : "f"(x));
    return r;
}

__device__ __forceinline__ void mma_tf32(float* d, const unsigned* a, const unsigned* b) {
    asm volatile(
        "mma.sync.aligned.m16n8k8.row.col.f32.tf32.tf32.f32 "
        "{%0,%1,%2,%3}, {%4,%5,%6,%7}, {%8,%9}, {%0,%1,%2,%3};"
        : "+f"(d[0]), "+f"(d[1]), "+f"(d[2]), "+f"(d[3])
        : "r"(a[0]), "r"(a[1]), "r"(a[2]), "r"(a[3]), "r"(b[0]), "r"(b[1]));
}

__device__ __forceinline__ void cp16(void* smem_dst, const void* gmem_src, bool pred) {
    unsigned saddr = (unsigned)__cvta_generic_to_shared(smem_dst);
    int sz = pred ? 16 : 0;
    asm volatile("cp.async.cg.shared.global [%0], [%1], 16, %2;\n"
                 :: "r"(saddr), "l"(gmem_src), "r"(sz));
}
__device__ __forceinline__ void cp_commit() {
    asm volatile("cp.async.commit_group;\n");
}
template <int N>
__device__ __forceinline__ void cp_wait() {
    asm volatile("cp.async.wait_group %0;\n" :: "n"(N));
}

// ---------------- tf32 conversion kernel ----------------
__global__ void cvt_tf32_vec(const float4* __restrict__ in, uint4* __restrict__ out,
                             int n4) {
    int i = blockIdx.x * blockDim.x + threadIdx.x;
    if (i < n4) {
        float4 v = in[i];
        uint4 o;
        o.x = f2tf32(v.x); o.y = f2tf32(v.y); o.z = f2tf32(v.z); o.w = f2tf32(v.w);
        out[i] = o;
    }
}

// ---------------- degree + CSR build ----------------
__global__ void degree_count(const int* __restrict__ src, const int* __restrict__ dst,
                             float* __restrict__ rdo, float* __restrict__ rdi,
                             int* __restrict__ cnt) {
    int idx = blockIdx.x * blockDim.x + threadIdx.x;
    if (idx >= RR * EE) return;
    int r = idx / EE;
    int d = dst[idx];
    atomicAdd(&rdo[(size_t)r * NN + src[idx]], 1.0f);
    atomicAdd(&rdi[(size_t)r * NN + d], 1.0f);
    atomicAdd(&cnt[(size_t)r * NN + d], 1);
}

__global__ void degree_finalize(float* __restrict__ p, int n) {
    int idx = blockIdx.x * blockDim.x + threadIdx.x;
    if (idx < n) p[idx] = rsqrtf(fmaxf(p[idx], 1.0f));
}

__global__ __launch_bounds__(1024) void scan_offsets(const int* __restrict__ cnt,
                                                     int* __restrict__ off) {
    int r = blockIdx.x;
    const int* c = cnt + (size_t)r * NN;
    int* o = off + (size_t)r * (NN + 1);
    __shared__ int warp_sums[32];
    __shared__ int s_carry;
    if (threadIdx.x == 0) s_carry = 0;
    __syncthreads();
    int lane = threadIdx.x & 31;
    int w = threadIdx.x >> 5;
    for (int base = 0; base < NN; base += 1024) {
        int idx = base + threadIdx.x;
        int val = (idx < NN) ? c[idx] : 0;
        int x = val;
#pragma unroll
        for (int s = 1; s < 32; s <<= 1) {
            int y = __shfl_up_sync(0xffffffffu, x, s);
            if (lane >= s) x += y;
        }
        if (lane == 31) warp_sums[w] = x;
        __syncthreads();
        if (w == 0) {
            int y = warp_sums[lane];
#pragma unroll
            for (int s = 1; s < 32; s <<= 1) {
                int z = __shfl_up_sync(0xffffffffu, y, s);
                if (lane >= s) y += z;
            }
            warp_sums[lane] = y;
        }
        __syncthreads();
        int excl = x - val + ((w > 0) ? warp_sums[w - 1] : 0) + s_carry;
        if (idx < NN) o[idx] = excl;
        int chunk_total = warp_sums[31];
        __syncthreads();
        if (threadIdx.x == 0) s_carry += chunk_total;
        __syncthreads();
    }
    if (threadIdx.x == 0) o[NN] = s_carry;
}

__global__ void build_adj(const int* __restrict__ dst, const int* __restrict__ off,
                          int* __restrict__ cur, int* __restrict__ eid) {
    int idx = blockIdx.x * blockDim.x + threadIdx.x;
    if (idx >= RR * EE) return;
    int r = idx / EE;
    int e = idx - r * EE;
    int d = dst[idx];
    int pos = atomicAdd(&cur[(size_t)r * NN + d], 1);
    eid[(size_t)r * EE + off[(size_t)r * (NN + 1) + d] + pos] = e;
}

// ---------------- batched TF32 tensor-core GEMM (3 weights, shared A) -------
// C_z[M,512] = A[M,512] @ W_z[512,512] (* rs_z[row]) (+ b_z[col]), z=0..2
// A, W pre-converted tf32 (u32). cp.async 2-stage pipeline.
#define A_STRIDE 36   // words; 144B = 9*16B -> cp.async aligned, conflict-free frags
#define B_STRIDE 136  // words; 544B = 34*16B
#define AS_WORDS (128 * A_STRIDE)
#define BS_WORDS (32 * B_STRIDE)
#define GEMM_SMEM ((2 * AS_WORDS + 2 * BS_WORDS) * 4)

struct G3 {
    const unsigned* W[3];
    float* C[3];
    const float* rs[3];
    const float* b[3];
};

__global__ __launch_bounds__(256) void tf32gemm3(
    const unsigned* __restrict__ A, G3 args, int M) {
    extern __shared__ unsigned sm[];
    unsigned* As = sm;                 // 2 stages
    unsigned* Bs = sm + 2 * AS_WORDS;  // 2 stages

    const int z = blockIdx.z;
    const unsigned* W = args.W[z];
    const int bm = blockIdx.y * 128;
    const int bn = blockIdx.x * 128;
    const int tid = threadIdx.x;
    const int warp = tid >> 5;
    const int lane = tid & 31;
    const int g = lane >> 2;
    const int t = lane & 3;
    const int wm = (warp >> 1) * 32;
    const int wn = (warp & 1) * 64;

    float acc[2][8][4];
#pragma unroll
    for (int i = 0; i < 2; i++)
#pragma unroll
        for (int j = 0; j < 8; j++)
#pragma unroll
            for (int q = 0; q < 4; q++) acc[i][j][q] = 0.0f;

    // per-thread load slots (4 chunks of 16B for A, 4 for B)
    int a_row[4], a_c4[4], b_kk[4], b_n4[4];
#pragma unroll
    for (int i = 0; i < 4; i++) {
        int slot = tid + i * 256;
        a_row[i] = slot >> 3;
        a_c4[i] = slot & 7;
        b_kk[i] = slot >> 5;
        b_n4[i] = slot & 31;
    }

#define LOAD_TILE(k0, st)                                                          \
    do {                                                                           \
        unsigned* as = As + (st)*AS_WORDS;                                         \
        unsigned* bs = Bs + (st)*BS_WORDS;                                         \
        _Pragma("unroll") for (int i = 0; i < 4; i++) {                            \
            int gr = bm + a_row[i];                                                \
            cp16(as + a_row[i] * A_STRIDE + a_c4[i] * 4,                           \
                 A + (size_t)gr * 512 + (k0) + a_c4[i] * 4, gr < M);               \
            cp16(bs + b_kk[i] * B_STRIDE + b_n4[i] * 4,                            \
                 W + (size_t)((k0) + b_kk[i]) * 512 + bn + b_n4[i] * 4, true);     \
        }                                                                          \
    } while (0)

    LOAD_TILE(0, 0);
    cp_commit();
    int stage = 0;
#pragma unroll 1
    for (int it = 0; it < 16; it++) {
        if (it + 1 < 16) {
            LOAD_TILE((it + 1) * 32, stage ^ 1);
            cp_commit();
            cp_wait<1>();
        } else {
            cp_wait<0>();
        }
        __syncthreads();
        const unsigned* as = As + stage * AS_WORDS;
        const unsigned* bs = Bs + stage * BS_WORDS;
#pragma unroll
        for (int ks = 0; ks < 4; ks++) {
            const int k = ks * 8;
            unsigned afr[2][4];
#pragma unroll
            for (int mt = 0; mt < 2; mt++) {
                int r = wm + mt * 16 + g;
                afr[mt][0] = as[r * A_STRIDE + k + t];
                afr[mt][1] = as[(r + 8) * A_STRIDE + k + t];
                afr[mt][2] = as[r * A_STRIDE + k + t + 4];
                afr[mt][3] = as[(r + 8) * A_STRIDE + k + t + 4];
            }
            unsigned bfr[8][2];
#pragma unroll
            for (int nt = 0; nt < 8; nt++) {
                int n = wn + nt * 8 + g;
                bfr[nt][0] = bs[(k + t) * B_STRIDE + n];
                bfr[nt][1] = bs[(k + t + 4) * B_STRIDE + n];
            }
#pragma unroll
            for (int mt = 0; mt < 2; mt++)
#pragma unroll
                for (int nt = 0; nt < 8; nt++)
                    mma_tf32(acc[mt][nt], afr[mt], bfr[nt]);
        }
        __syncthreads();
        stage ^= 1;
    }

    float* C = args.C[z];
    const float* rowscale = args.rs[z];
    const float* bias = args.b[z];
#pragma unroll
    for (int mt = 0; mt < 2; mt++) {
        int r0 = bm + wm + mt * 16 + g;
        int r1 = r0 + 8;
        float s0 = 1.0f, s1 = 1.0f;
        if (rowscale) {
            if (r0 < M) s0 = rowscale[r0];
            if (r1 < M) s1 = rowscale[r1];
        }
#pragma unroll
        for (int nt = 0; nt < 8; nt++) {
            int c = bn + wn + nt * 8 + t * 2;
            float b0 = 0.0f, b1 = 0.0f;
            if (bias) { b0 = bias[c]; b1 = bias[c + 1]; }
            if (r0 < M) {
                float2 v = make_float2(acc[mt][nt][0] * s0 + b0,
                                       acc[mt][nt][1] * s0 + b1);
                *(float2*)(C + (size_t)r0 * 512 + c) = v;
            }
            if (r1 < M) {
                float2 v = make_float2(acc[mt][nt][2] * s1 + b0,
                                       acc[mt][nt][3] * s1 + b1);
                *(float2*)(C + (size_t)r1 * 512 + c) = v;
            }
        }
    }
}

// ---------------- LN core: returns normalized/ELU'd 4 values -----------------
__device__ __forceinline__ float4 ln_elu_core4(
    float4 v, const float* __restrict__ gamma, const float* __restrict__ beta) {
    int t = threadIdx.x;
    float sum = v.x + v.y + v.z + v.w;
    sum = block_reduce_sum_128(sum);
    float u = sum * (1.0f / HH);
    float dx = v.x - u, dy = v.y - u, dz = v.z - u, dw = v.w - u;
    float var = dx * dx + dy * dy + dz * dz + dw * dw;
    var = block_reduce_sum_128(var) * (1.0f / HH);
    float inv = rsqrtf(var + 1e-12f);
    float4 ga = ((const float4*)gamma)[t];
    float4 be = ((const float4*)beta)[t];
    float y0 = ga.x * dx * inv + be.x;
    float y1 = ga.y * dy * inv + be.y;
    float y2 = ga.z * dz * inv + be.z;
    float y3 = ga.w * dw * inv + be.w;
    y0 = (y0 > 0.0f) ? y0 : (expf(y0) - 1.0f);
    y1 = (y1 > 0.0f) ? y1 : (expf(y1) - 1.0f);
    y2 = (y2 > 0.0f) ? y2 : (expf(y2) - 1.0f);
    y3 = (y3 > 0.0f) ? y3 : (expf(y3) - 1.0f);
    return make_float4(y0, y1, y2, y3);
}

// ---------------- fused conv gather + LN + ELU (store f32 stk) ----------------
__global__ __launch_bounds__(128) void conv_gather_ln(
    const int* __restrict__ eid, const int* __restrict__ off,
    const int* __restrict__ src, const float* __restrict__ X,
    const float* __restrict__ rdi, const float* __restrict__ bias,
    const float* __restrict__ gamma, const float* __restrict__ beta,
    float* __restrict__ out) {
    int n = blockIdx.x;
    int p0 = off[n], p1 = off[n + 1];
    int t = threadIdx.x;
    float4 acc = make_float4(0.f, 0.f, 0.f, 0.f);
    for (int p = p0; p < p1; p++) {
        int sn = src[eid[p]];
        float4 rv = ((const float4*)(X + (size_t)sn * HH))[t];
        acc.x += rv.x; acc.y += rv.y; acc.z += rv.z; acc.w += rv.w;
    }
    float sc = rdi[n];
    float4 bb = ((const float4*)bias)[t];
    float4 v = make_float4(acc.x * sc + bb.x, acc.y * sc + bb.y,
                           acc.z * sc + bb.z, acc.w * sc + bb.w);
    float4 y = ln_elu_core4(v, gamma, beta);
    ((float4*)(out + (size_t)n * (RR * HH)))[t] = y;
}

// ---------------- fused GAT gather + LN + ELU (accumulate f32 stk) ------------
__global__ __launch_bounds__(128) void gat_gather_ln(
    const int* __restrict__ eid, const int* __restrict__ off,
    const int* __restrict__ src, const float* __restrict__ f,
    const float* __restrict__ e_arr, const float* __restrict__ s_arr,
    const float* __restrict__ bias, const float* __restrict__ gamma,
    const float* __restrict__ beta, float* __restrict__ out) {
    int n = blockIdx.x;
    int p0 = off[n], p1 = off[n + 1];
    int t = threadIdx.x;
    int h = t >> 4;
    float sv = s_arr[n * NHEADS + h];
    float invs = (sv > 0.0f) ? (1.0f / sv) : 1.0f;
    float4 acc = make_float4(0.f, 0.f, 0.f, 0.f);
    for (int p = p0; p < p1; p++) {
        int e = eid[p];
        int sn = src[e];
        float a = e_arr[(size_t)e * NHEADS + h] * invs;
        float4 rv = ((const float4*)(f + (size_t)sn * HH))[t];
        acc.x += a * rv.x; acc.y += a * rv.y;
        acc.z += a * rv.z; acc.w += a * rv.w;
    }
    float4 bb = ((const float4*)bias)[t];
    float4 v = make_float4(acc.x + bb.x, acc.y + bb.y, acc.z + bb.z, acc.w + bb.w);
    float4 y = ln_elu_core4(v, gamma, beta);
    float4* o = (float4*)(out + (size_t)n * (RR * HH)) + t;
    float4 old = *o;
    *o = make_float4(y.x + old.x, y.y + old.y, y.z + old.z, y.w + old.w);
}

// ---------------- skip LN: add to f32 partial, emit tf32 stk32 ----------------
__global__ __launch_bounds__(128) void skip_ln(
    const float* __restrict__ X, const float* __restrict__ bias,
    const float* __restrict__ gamma, const float* __restrict__ beta,
    const float* __restrict__ partial, unsigned* __restrict__ out32) {
    int n = blockIdx.x;
    int t = threadIdx.x;
    float4 x = ((const float4*)(X + (size_t)n * HH))[t];
    float4 bb = ((const float4*)bias)[t];
    float4 v = make_float4(x.x + bb.x, x.y + bb.y, x.z + bb.z, x.w + bb.w);
    float4 y = ln_elu_core4(v, gamma, beta);
    float4 old = ((const float4*)(partial + (size_t)n * (RR * HH)))[t];
    uint4 o;
    o.x = f2tf32(y.x + old.x);
    o.y = f2tf32(y.y + old.y);
    o.z = f2tf32(y.z + old.z);
    o.w = f2tf32(y.w + old.w);
    ((uint4*)(out32 + (size_t)n * (RR * HH)))[t] = o;
}

__global__ void init_ms(float* __restrict__ m, float* __restrict__ s) {
    int idx = blockIdx.x * blockDim.x + threadIdx.x;
    if (idx < NN * NHEADS) { m[idx] = -INFINITY; s[idx] = 0.0f; }
}

// ---------------- GAT edge-stat kernels ----------------
__global__ void gat_el_er(const float* __restrict__ f, const float* __restrict__ al,
                          const float* __restrict__ ar, float* __restrict__ el,
                          float* __restrict__ er) {
    int idx = blockIdx.x * blockDim.x + threadIdx.x;
    if (idx >= NN * NHEADS) return;
    int n = idx >> 3;
    int hh = idx & 7;
    const float* fr = f + (size_t)n * HH + hh * DHH;
    const float* a1 = al + hh * DHH;
    const float* a2 = ar + hh * DHH;
    float s1 = 0.0f, s2 = 0.0f;
#pragma unroll 8
    for (int d = 0; d < DHH; d++) {
        float fv = fr[d];
        s1 += fv * a1[d];
        s2 += fv * a2[d];
    }
    el[idx] = s1;
    er[idx] = s2;
}

__global__ void gat_edge1(const int* __restrict__ src, const int* __restrict__ dst,
                          const float* __restrict__ el, const float* __restrict__ er,
                          float* __restrict__ e, float* __restrict__ m) {
    int idx = blockIdx.x * blockDim.x + threadIdx.x;
    if (idx >= EE * NHEADS) return;
    int ed = idx >> 3;
    int hh = idx & 7;
    float x = el[src[ed] * NHEADS + hh] + er[dst[ed] * NHEADS + hh];
    x = (x > 0.0f) ? x : 0.2f * x;
    e[idx] = x;
    atomicMaxFloat(&m[dst[ed] * NHEADS + hh], x);
}

__global__ void gat_edge2(const int* __restrict__ dst, float* __restrict__ e,
                          const float* __restrict__ m, float* __restrict__ s) {
    int idx = blockIdx.x * blockDim.x + threadIdx.x;
    if (idx >= EE * NHEADS) return;
    int ed = idx >> 3;
    int hh = idx & 7;
    float ex = expf(e[idx] - m[dst[ed] * NHEADS + hh]);
    e[idx] = ex;
    atomicAdd(&s[dst[ed] * NHEADS + hh], ex);
}

// ---------------- relation MHA (3 tokens) + mean; writes f32 h and tf32 h32 --
__global__ __launch_bounds__(256) void mha_mean(
    const float* __restrict__ q, const float* __restrict__ k,
    const float* __restrict__ v, float* __restrict__ out,
    unsigned* __restrict__ out32) {
    int n = blockIdx.x;
    int hd = threadIdx.x >> 5;
    int lane = threadIdx.x & 31;
    size_t base = (size_t)n * RR * HH + hd * DHH;
    float qa[RR], qb[RR], ka[RR], kb[RR], va[RR], vb[RR];
#pragma unroll
    for (int r = 0; r < RR; r++) {
        size_t off = base + (size_t)r * HH;
        qa[r] = q[off + lane];
        qb[r] = q[off + lane + 32];
        ka[r] = k[off + lane];
        kb[r] = k[off + lane + 32];
        va[r] = v[off + lane];
        vb[r] = v[off + lane + 32];
    }
    float sc[RR][RR];
#pragma unroll
    for (int r = 0; r < RR; r++)
#pragma unroll
        for (int t = 0; t < RR; t++) {
            float p = qa[r] * ka[t] + qb[r] * kb[t];
#pragma unroll
            for (int o = 16; o > 0; o >>= 1) p += __shfl_xor_sync(0xffffffffu, p, o);
            sc[r][t] = p * 0.125f;
        }
    float w0 = 0.0f, w1 = 0.0f, w2 = 0.0f;
#pragma unroll
    for (int r = 0; r < RR; r++) {
        float mx = fmaxf(sc[r][0], fmaxf(sc[r][1], sc[r][2]));
        float e0 = expf(sc[r][0] - mx);
        float e1 = expf(sc[r][1] - mx);
        float e2 = expf(sc[r][2] - mx);
        float inv = 1.0f / (e0 + e1 + e2);
        w0 += e0 * inv;
        w1 += e1 * inv;
        w2 += e2 * inv;
    }
    const float third = 1.0f / 3.0f;
    float oa = (w0 * va[0] + w1 * va[1] + w2 * va[2]) * third;
    float ob = (w0 * vb[0] + w1 * vb[1] + w2 * vb[2]) * third;
    size_t o0 = (size_t)n * HH + hd * DHH + lane;
    out[o0] = oa;
    out[o0 + 32] = ob;
    out32[o0] = f2tf32(oa);
    out32[o0 + 32] = f2tf32(ob);
}

// ---------------- classifier ----------------
__global__ void classify(const float* __restrict__ h, const float* __restrict__ W,
                         const float* __restrict__ b, float* __restrict__ out) {
    int idx = blockIdx.x * blockDim.x + threadIdx.x;
    if (idx >= NN * NCLSS) return;
    int n = idx / NCLSS;
    int c = idx % NCLSS;
    const float* hr = h + (size_t)n * HH;
    float sum = b[c];
#pragma unroll 8
    for (int j = 0; j < HH; j++) sum += hr[j] * W[j * NCLSS + c];
    out[idx] = sum;
}

// ---------------- launch ----------------
extern "C" void kernel_launch(void* const* d_in, const int* in_sizes, int n_in,
                              void* d_out, int out_size) {
    const float* feature = (const float*)d_in[0];
    const int* src = (const int*)d_in[1];
    const int* dst = (const int*)d_in[2];
    const float* Wc = (const float*)d_in[3];
    const float* bc = (const float*)d_in[4];
    const float* gc = (const float*)d_in[5];
    const float* betac = (const float*)d_in[6];
    const float* Wg = (const float*)d_in[7];
    const float* bg = (const float*)d_in[8];
    const float* al = (const float*)d_in[9];
    const float* ar = (const float*)d_in[10];
    const float* gg = (const float*)d_in[11];
    const float* betag = (const float*)d_in[12];
    const float* Ws = (const float*)d_in[13];
    const float* bs = (const float*)d_in[14];
    const float* gs = (const float*)d_in[15];
    const float* betas = (const float*)d_in[16];
    const float* Wq = (const float*)d_in[17];
    const float* bq = (const float*)d_in[18];
    const float* Wk = (const float*)d_in[19];
    const float* bk = (const float*)d_in[20];
    const float* Wv = (const float*)d_in[21];
    const float* bv = (const float*)d_in[22];
    const float* Wout = (const float*)d_in[23];
    const float* bout = (const float*)d_in[24];
    float* out = (float*)d_out;

    float *p_h, *p_tmp, *p_tmp2, *p_f, *p_stk, *p_q, *p_k, *p_v;
    float *p_rdo, *p_rdi, *p_el, *p_er, *p_m, *p_s, *p_e;
    unsigned *p_h32, *p_stk32, *p_w32;
    int *p_cnt, *p_cur, *p_off, *p_eid;
    cudaGetSymbolAddress((void**)&p_h, g_h);
    cudaGetSymbolAddress((void**)&p_h32, g_h32);
    cudaGetSymbolAddress((void**)&p_tmp, g_tmp);
    cudaGetSymbolAddress((void**)&p_tmp2, g_tmp2);
    cudaGetSymbolAddress((void**)&p_f, g_f);
    cudaGetSymbolAddress((void**)&p_stk, g_stk);
    cudaGetSymbolAddress((void**)&p_stk32, g_stk32);
    cudaGetSymbolAddress((void**)&p_q, g_q);
    cudaGetSymbolAddress((void**)&p_k, g_k);
    cudaGetSymbolAddress((void**)&p_v, g_v);
    cudaGetSymbolAddress((void**)&p_w32, g_w32);
    cudaGetSymbolAddress((void**)&p_rdo, g_rdo);
    cudaGetSymbolAddress((void**)&p_rdi, g_rdi);
    cudaGetSymbolAddress((void**)&p_el, g_el);
    cudaGetSymbolAddress((void**)&p_er, g_er);
    cudaGetSymbolAddress((void**)&p_m, g_m);
    cudaGetSymbolAddress((void**)&p_s, g_s);
    cudaGetSymbolAddress((void**)&p_e, g_e);
    cudaGetSymbolAddress((void**)&p_cnt, g_cnt);
    cudaGetSymbolAddress((void**)&p_cur, g_cur);
    cudaGetSymbolAddress((void**)&p_off, g_off);
    cudaGetSymbolAddress((void**)&p_eid, g_eid);

    cudaFuncSetAttribute(tf32gemm3, cudaFuncAttributeMaxDynamicSharedMemorySize,
                         GEMM_SMEM);

    // weight offsets in g_w32
    const size_t WHH = (size_t)HH * HH;
    unsigned* w32_Wc = p_w32;               // 6 matrices
    unsigned* w32_Wg = p_w32 + 6 * WHH;     // 6
    unsigned* w32_Ws = p_w32 + 12 * WHH;    // 6
    unsigned* w32_Wq = p_w32 + 18 * WHH;    // 2
    unsigned* w32_Wk = p_w32 + 20 * WHH;    // 2
    unsigned* w32_Wv = p_w32 + 22 * WHH;    // 2

    // pre-convert weights + feature to tf32
    {
        int n4 = (int)(6 * WHH / 4);
        int blocks = (n4 + 255) / 256;
        cvt_tf32_vec<<<blocks, 256>>>((const float4*)Wc, (uint4*)w32_Wc, n4);
        cvt_tf32_vec<<<blocks, 256>>>((const float4*)Wg, (uint4*)w32_Wg, n4);
        cvt_tf32_vec<<<blocks, 256>>>((const float4*)Ws, (uint4*)w32_Ws, n4);
        int n4q = (int)(2 * WHH / 4);
        int blocksq = (n4q + 255) / 256;
        cvt_tf32_vec<<<blocksq, 256>>>((const float4*)Wq, (uint4*)w32_Wq, n4q);
        cvt_tf32_vec<<<blocksq, 256>>>((const float4*)Wk, (uint4*)w32_Wk, n4q);
        cvt_tf32_vec<<<blocksq, 256>>>((const float4*)Wv, (uint4*)w32_Wv, n4q);
        int n4f = (int)((size_t)NN * HH / 4);
        cvt_tf32_vec<<<(n4f + 255) / 256, 256>>>((const float4*)feature,
                                                 (uint4*)p_h32, n4f);
    }

    // degrees + CSR (same graph for both layers)
    cudaMemsetAsync(p_rdo, 0, (size_t)RR * NN * sizeof(float), 0);
    cudaMemsetAsync(p_rdi, 0, (size_t)RR * NN * sizeof(float), 0);
    cudaMemsetAsync(p_cnt, 0, (size_t)RR * NN * sizeof(int), 0);
    cudaMemsetAsync(p_cur, 0, (size_t)RR * NN * sizeof(int), 0);
    degree_count<<<(RR * EE + 255) / 256, 256>>>(src, dst, p_rdo, p_rdi, p_cnt);
    degree_finalize<<<(RR * NN + 255) / 256, 256>>>(p_rdo, RR * NN);
    degree_finalize<<<(RR * NN + 255) / 256, 256>>>(p_rdi, RR * NN);
    scan_offsets<<<RR, 1024>>>(p_cnt, p_off);
    build_adj<<<(RR * EE + 255) / 256, 256>>>(dst, p_off, p_cur, p_eid);

    const dim3 gemm_grid_n(4, (NN + 127) / 128, 3);
    const dim3 gemm_grid_nr(4, (NN * RR + 127) / 128, 3);
    const int ehd_blocks = (EE * NHEADS + 255) / 256;
    const int nhd_blocks = (NN * NHEADS + 255) / 256;

    for (int l = 0; l < LL; l++) {
        for (int r = 0; r < RR; r++) {
            const size_t lr = (size_t)(l * RR + r);
            const float* bc_lr = bc + lr * HH;
            const float* gc_lr = gc + lr * HH;
            const float* betac_lr = betac + lr * HH;
            const float* bg_lr = bg + lr * HH;
            const float* gg_lr = gg + lr * HH;
            const float* betag_lr = betag + lr * HH;
            const float* bs_lr = bs + lr * HH;
            const float* gs_lr = gs + lr * HH;
            const float* betas_lr = betas + lr * HH;
            const float* al_lr = al + lr * NHEADS * DHH;
            const float* ar_lr = ar + lr * NHEADS * DHH;
            const int* src_r = src + (size_t)r * EE;
            const int* dst_r = dst + (size_t)r * EE;
            const int* eid_r = p_eid + (size_t)r * EE;
            const int* off_r = p_off + (size_t)r * (NN + 1);

            // ---- batched GEMM: z0=conv(W_c, rowscale), z1=gat(W_g), z2=skip(W_s)
            G3 a3;
            a3.W[0] = w32_Wc + lr * WHH;
            a3.W[1] = w32_Wg + lr * WHH;
            a3.W[2] = w32_Ws + lr * WHH;
            a3.C[0] = p_tmp;
            a3.C[1] = p_f;
            a3.C[2] = p_tmp2;
            a3.rs[0] = p_rdo + (size_t)r * NN;
            a3.rs[1] = nullptr;
            a3.rs[2] = nullptr;
            a3.b[0] = nullptr;
            a3.b[1] = nullptr;
            a3.b[2] = nullptr;
            tf32gemm3<<<gemm_grid_n, 256, GEMM_SMEM>>>(p_h32, a3, NN);

            // ---- GraphConv gather + LN (store) ----
            conv_gather_ln<<<NN, 128>>>(eid_r, off_r, src_r, p_tmp,
                                        p_rdi + (size_t)r * NN, bc_lr, gc_lr,
                                        betac_lr, p_stk + (size_t)r * HH);

            // ---- GAT stats + gather + LN (accumulate) ----
            gat_el_er<<<nhd_blocks, 256>>>(p_f, al_lr, ar_lr, p_el, p_er);
            init_ms<<<nhd_blocks, 256>>>(p_m, p_s);
            gat_edge1<<<ehd_blocks, 256>>>(src_r, dst_r, p_el, p_er, p_e, p_m);
            gat_edge2<<<ehd_blocks, 256>>>(dst_r, p_e, p_m, p_s);
            gat_gather_ln<<<NN, 128>>>(eid_r, off_r, src_r, p_f, p_e, p_s,
                                       bg_lr, gg_lr, betag_lr,
                                       p_stk + (size_t)r * HH);

            // ---- skip LN (adds partial, emits tf32 stk32) ----
            skip_ln<<<NN, 128>>>(p_tmp2, bs_lr, gs_lr, betas_lr,
                                 p_stk + (size_t)r * HH,
                                 p_stk32 + (size_t)r * HH);
        }

        // ---- relation MHA: batched QKV GEMM ----
        G3 aq;
        aq.W[0] = w32_Wq + (size_t)l * WHH;
        aq.W[1] = w32_Wk + (size_t)l * WHH;
        aq.W[2] = w32_Wv + (size_t)l * WHH;
        aq.C[0] = p_q;
        aq.C[1] = p_k;
        aq.C[2] = p_v;
        aq.rs[0] = nullptr; aq.rs[1] = nullptr; aq.rs[2] = nullptr;
        aq.b[0] = bq + (size_t)l * HH;
        aq.b[1] = bk + (size_t)l * HH;
        aq.b[2] = bv + (size_t)l * HH;
        tf32gemm3<<<gemm_grid_nr, 256, GEMM_SMEM>>>(p_stk32, aq, NN * RR);

        mha_mean<<<NN, 256>>>(p_q, p_k, p_v, p_h, p_h32);
    }

    classify<<<(NN * NCLSS + 255) / 256, 256>>>(p_h, Wout, bout, out);
}

// round 7
// speedup vs baseline: 3.1824x; 1.0256x over previous
#include <cuda_runtime.h>
#include <math.h>

#define NN 50000
#define EE 150000
#define RR 3
#define LL 2
#define HH 512
#define NHEADS 8
#define DHH 64
#define NCLSS 23

// ---------------- scratch (device globals; no allocs allowed) ----------------
__device__ float g_h[(size_t)NN * HH];
__device__ unsigned g_h32[(size_t)NN * HH];
__device__ float g_tmp[(size_t)NN * HH];
__device__ float g_tmp2[(size_t)NN * HH];
__device__ float g_f[(size_t)NN * HH];
__device__ unsigned g_stk32[(size_t)NN * RR * HH];
__device__ float g_q[(size_t)NN * RR * HH];
__device__ float g_k[(size_t)NN * RR * HH];
__device__ float g_v[(size_t)NN * RR * HH];
__device__ unsigned g_w32[(size_t)24 * HH * HH];  // Wc(6) Wg(6) Ws(6) Wq(2) Wk(2) Wv(2)
__device__ float g_rdo[(size_t)RR * NN];
__device__ float g_rdi[(size_t)RR * NN];
__device__ float g_el[(size_t)NN * NHEADS];
__device__ float g_er[(size_t)NN * NHEADS];
// CSR (dst-indexed) per relation
__device__ int g_cnt[(size_t)RR * NN];
__device__ int g_cur[(size_t)RR * NN];
__device__ int g_off[(size_t)RR * (NN + 1)];
__device__ int g_eid[(size_t)RR * EE];

// ---------------- helpers ----------------
__device__ __forceinline__ float block_reduce_sum_128(float val) {
    __shared__ float sh[32];
    __syncthreads();
    int lane = threadIdx.x & 31;
    int wid = threadIdx.x >> 5;
#pragma unroll
    for (int o = 16; o > 0; o >>= 1) val += __shfl_xor_sync(0xffffffffu, val, o);
    if (lane == 0) sh[wid] = val;
    __syncthreads();
    if (wid == 0) {
        float v = (lane < (blockDim.x >> 5)) ? sh[lane] : 0.0f;
#pragma unroll
        for (int o = 16; o > 0; o >>= 1) v += __shfl_xor_sync(0xffffffffu, v, o);
        if (lane == 0) sh[0] = v;
    }
    __syncthreads();
    return sh[0];
}

__device__ __forceinline__ unsigned f2tf32(float x) {
    unsigned r;
    asm("cvt.rna.tf32.f32 %0, %1;" : "=r"(r) : "f"(x));
    return r;
}

__device__ __forceinline__ void mma_tf32(float* d, const unsigned* a, const unsigned* b) {
    asm volatile(
        "mma.sync.aligned.m16n8k8.row.col.f32.tf32.tf32.f32 "
        "{%0,%1,%2,%3}, {%4,%5,%6,%7}, {%8,%9}, {%0,%1,%2,%3};"
        : "+f"(d[0]), "+f"(d[1]), "+f"(d[2]), "+f"(d[3])
        : "r"(a[0]), "r"(a[1]), "r"(a[2]), "r"(a[3]), "r"(b[0]), "r"(b[1]));
}

__device__ __forceinline__ void cp16(void* smem_dst, const void* gmem_src, bool pred) {
    unsigned saddr = (unsigned)__cvta_generic_to_shared(smem_dst);
    int sz = pred ? 16 : 0;
    asm volatile("cp.async.cg.shared.global [%0], [%1], 16, %2;\n"
                 :: "r"(saddr), "l"(gmem_src), "r"(sz));
}
__device__ __forceinline__ void cp_commit() {
    asm volatile("cp.async.commit_group;\n");
}
template <int N>
__device__ __forceinline__ void cp_wait() {
    asm volatile("cp.async.wait_group %0;\n" :: "n"(N));
}

// ---------------- tf32 conversion kernel ----------------
__global__ void cvt_tf32_vec(const float4* __restrict__ in, uint4* __restrict__ out,
                             int n4) {
    int i = blockIdx.x * blockDim.x + threadIdx.x;
    if (i < n4) {
        float4 v = in[i];
        uint4 o;
        o.x = f2tf32(v.x); o.y = f2tf32(v.y); o.z = f2tf32(v.z); o.w = f2tf32(v.w);
        out[i] = o;
    }
}

// ---------------- degree + CSR build ----------------
__global__ void degree_count(const int* __restrict__ src, const int* __restrict__ dst,
                             float* __restrict__ rdo, float* __restrict__ rdi,
                             int* __restrict__ cnt) {
    int idx = blockIdx.x * blockDim.x + threadIdx.x;
    if (idx >= RR * EE) return;
    int r = idx / EE;
    int d = dst[idx];
    atomicAdd(&rdo[(size_t)r * NN + src[idx]], 1.0f);
    atomicAdd(&rdi[(size_t)r * NN + d], 1.0f);
    atomicAdd(&cnt[(size_t)r * NN + d], 1);
}

__global__ void degree_finalize(float* __restrict__ p, int n) {
    int idx = blockIdx.x * blockDim.x + threadIdx.x;
    if (idx < n) p[idx] = rsqrtf(fmaxf(p[idx], 1.0f));
}

__global__ __launch_bounds__(1024) void scan_offsets(const int* __restrict__ cnt,
                                                     int* __restrict__ off) {
    int r = blockIdx.x;
    const int* c = cnt + (size_t)r * NN;
    int* o = off + (size_t)r * (NN + 1);
    __shared__ int warp_sums[32];
    __shared__ int s_carry;
    if (threadIdx.x == 0) s_carry = 0;
    __syncthreads();
    int lane = threadIdx.x & 31;
    int w = threadIdx.x >> 5;
    for (int base = 0; base < NN; base += 1024) {
        int idx = base + threadIdx.x;
        int val = (idx < NN) ? c[idx] : 0;
        int x = val;
#pragma unroll
        for (int s = 1; s < 32; s <<= 1) {
            int y = __shfl_up_sync(0xffffffffu, x, s);
            if (lane >= s) x += y;
        }
        if (lane == 31) warp_sums[w] = x;
        __syncthreads();
        if (w == 0) {
            int y = warp_sums[lane];
#pragma unroll
            for (int s = 1; s < 32; s <<= 1) {
                int z = __shfl_up_sync(0xffffffffu, y, s);
                if (lane >= s) y += z;
            }
            warp_sums[lane] = y;
        }
        __syncthreads();
        int excl = x - val + ((w > 0) ? warp_sums[w - 1] : 0) + s_carry;
        if (idx < NN) o[idx] = excl;
        int chunk_total = warp_sums[31];
        __syncthreads();
        if (threadIdx.x == 0) s_carry += chunk_total;
        __syncthreads();
    }
    if (threadIdx.x == 0) o[NN] = s_carry;
}

__global__ void build_adj(const int* __restrict__ dst, const int* __restrict__ off,
                          int* __restrict__ cur, int* __restrict__ eid) {
    int idx = blockIdx.x * blockDim.x + threadIdx.x;
    if (idx >= RR * EE) return;
    int r = idx / EE;
    int e = idx - r * EE;
    int d = dst[idx];
    int pos = atomicAdd(&cur[(size_t)r * NN + d], 1);
    eid[(size_t)r * EE + off[(size_t)r * (NN + 1) + d] + pos] = e;
}

// ---------------- batched TF32 tensor-core GEMM (3 weights, shared A) -------
#define A_STRIDE 36
#define B_STRIDE 136
#define AS_WORDS (128 * A_STRIDE)
#define BS_WORDS (32 * B_STRIDE)
#define GEMM_SMEM ((2 * AS_WORDS + 2 * BS_WORDS) * 4)

struct G3 {
    const unsigned* W[3];
    float* C[3];
    const float* rs[3];
    const float* b[3];
};

__global__ __launch_bounds__(256) void tf32gemm3(
    const unsigned* __restrict__ A, G3 args, int M) {
    extern __shared__ unsigned sm[];
    unsigned* As = sm;
    unsigned* Bs = sm + 2 * AS_WORDS;

    const int z = blockIdx.z;
    const unsigned* W = args.W[z];
    const int bm = blockIdx.y * 128;
    const int bn = blockIdx.x * 128;
    const int tid = threadIdx.x;
    const int warp = tid >> 5;
    const int lane = tid & 31;
    const int g = lane >> 2;
    const int t = lane & 3;
    const int wm = (warp >> 1) * 32;
    const int wn = (warp & 1) * 64;

    float acc[2][8][4];
#pragma unroll
    for (int i = 0; i < 2; i++)
#pragma unroll
        for (int j = 0; j < 8; j++)
#pragma unroll
            for (int q = 0; q < 4; q++) acc[i][j][q] = 0.0f;

    int a_row[4], a_c4[4], b_kk[4], b_n4[4];
#pragma unroll
    for (int i = 0; i < 4; i++) {
        int slot = tid + i * 256;
        a_row[i] = slot >> 3;
        a_c4[i] = slot & 7;
        b_kk[i] = slot >> 5;
        b_n4[i] = slot & 31;
    }

#define LOAD_TILE(k0, st)                                                          \
    do {                                                                           \
        unsigned* as = As + (st)*AS_WORDS;                                         \
        unsigned* bs = Bs + (st)*BS_WORDS;                                         \
        _Pragma("unroll") for (int i = 0; i < 4; i++) {                            \
            int gr = bm + a_row[i];                                                \
            cp16(as + a_row[i] * A_STRIDE + a_c4[i] * 4,                           \
                 A + (size_t)gr * 512 + (k0) + a_c4[i] * 4, gr < M);               \
            cp16(bs + b_kk[i] * B_STRIDE + b_n4[i] * 4,                            \
                 W + (size_t)((k0) + b_kk[i]) * 512 + bn + b_n4[i] * 4, true);     \
        }                                                                          \
    } while (0)

    LOAD_TILE(0, 0);
    cp_commit();
    int stage = 0;
#pragma unroll 1
    for (int it = 0; it < 16; it++) {
        if (it + 1 < 16) {
            LOAD_TILE((it + 1) * 32, stage ^ 1);
            cp_commit();
            cp_wait<1>();
        } else {
            cp_wait<0>();
        }
        __syncthreads();
        const unsigned* as = As + stage * AS_WORDS;
        const unsigned* bs = Bs + stage * BS_WORDS;
#pragma unroll
        for (int ks = 0; ks < 4; ks++) {
            const int k = ks * 8;
            unsigned afr[2][4];
#pragma unroll
            for (int mt = 0; mt < 2; mt++) {
                int r = wm + mt * 16 + g;
                afr[mt][0] = as[r * A_STRIDE + k + t];
                afr[mt][1] = as[(r + 8) * A_STRIDE + k + t];
                afr[mt][2] = as[r * A_STRIDE + k + t + 4];
                afr[mt][3] = as[(r + 8) * A_STRIDE + k + t + 4];
            }
            unsigned bfr[8][2];
#pragma unroll
            for (int nt = 0; nt < 8; nt++) {
                int n = wn + nt * 8 + g;
                bfr[nt][0] = bs[(k + t) * B_STRIDE + n];
                bfr[nt][1] = bs[(k + t + 4) * B_STRIDE + n];
            }
#pragma unroll
            for (int mt = 0; mt < 2; mt++)
#pragma unroll
                for (int nt = 0; nt < 8; nt++)
                    mma_tf32(acc[mt][nt], afr[mt], bfr[nt]);
        }
        __syncthreads();
        stage ^= 1;
    }

    float* C = args.C[z];
    const float* rowscale = args.rs[z];
    const float* bias = args.b[z];
#pragma unroll
    for (int mt = 0; mt < 2; mt++) {
        int r0 = bm + wm + mt * 16 + g;
        int r1 = r0 + 8;
        float s0 = 1.0f, s1 = 1.0f;
        if (rowscale) {
            if (r0 < M) s0 = rowscale[r0];
            if (r1 < M) s1 = rowscale[r1];
        }
#pragma unroll
        for (int nt = 0; nt < 8; nt++) {
            int c = bn + wn + nt * 8 + t * 2;
            float b0 = 0.0f, b1 = 0.0f;
            if (bias) { b0 = bias[c]; b1 = bias[c + 1]; }
            if (r0 < M) {
                float2 v = make_float2(acc[mt][nt][0] * s0 + b0,
                                       acc[mt][nt][1] * s0 + b1);
                *(float2*)(C + (size_t)r0 * 512 + c) = v;
            }
            if (r1 < M) {
                float2 v = make_float2(acc[mt][nt][2] * s1 + b0,
                                       acc[mt][nt][3] * s1 + b1);
                *(float2*)(C + (size_t)r1 * 512 + c) = v;
            }
        }
    }
}

// ---------------- LN core: returns normalized/ELU'd 4 values -----------------
__device__ __forceinline__ float4 ln_elu_core4(
    float4 v, const float* __restrict__ gamma, const float* __restrict__ beta) {
    int t = threadIdx.x;
    float sum = v.x + v.y + v.z + v.w;
    sum = block_reduce_sum_128(sum);
    float u = sum * (1.0f / HH);
    float dx = v.x - u, dy = v.y - u, dz = v.z - u, dw = v.w - u;
    float var = dx * dx + dy * dy + dz * dz + dw * dw;
    var = block_reduce_sum_128(var) * (1.0f / HH);
    float inv = rsqrtf(var + 1e-12f);
    float4 ga = ((const float4*)gamma)[t];
    float4 be = ((const float4*)beta)[t];
    float y0 = ga.x * dx * inv + be.x;
    float y1 = ga.y * dy * inv + be.y;
    float y2 = ga.z * dz * inv + be.z;
    float y3 = ga.w * dw * inv + be.w;
    y0 = (y0 > 0.0f) ? y0 : (expf(y0) - 1.0f);
    y1 = (y1 > 0.0f) ? y1 : (expf(y1) - 1.0f);
    y2 = (y2 > 0.0f) ? y2 : (expf(y2) - 1.0f);
    y3 = (y3 > 0.0f) ? y3 : (expf(y3) - 1.0f);
    return make_float4(y0, y1, y2, y3);
}

// ---------------- mega-fused per-node branch kernel --------------------------
// conv gather+LN + GAT softmax+gather+LN + skip LN, summed, emitted as tf32.
__global__ __launch_bounds__(128) void fused_branches(
    const int* __restrict__ eid, const int* __restrict__ off,
    const int* __restrict__ src,
    const float* __restrict__ Xc,      // conv GEMM out (rowscaled)
    const float* __restrict__ f,       // gat GEMM out
    const float* __restrict__ Xs,      // skip GEMM out
    const float* __restrict__ el, const float* __restrict__ er,
    const float* __restrict__ rdi,
    const float* __restrict__ bc, const float* __restrict__ gc,
    const float* __restrict__ bec,
    const float* __restrict__ bg, const float* __restrict__ gg,
    const float* __restrict__ beg,
    const float* __restrict__ bs_, const float* __restrict__ gs,
    const float* __restrict__ bes,
    unsigned* __restrict__ out32) {
    int n = blockIdx.x;
    int p0 = off[n], p1 = off[n + 1];
    int t = threadIdx.x;
    int h = t >> 4;  // head for cols 4t..4t+3

    __shared__ float sh_m[NHEADS], sh_invs[NHEADS];
    // GAT softmax stats: threads 0..7, one head each (deg is tiny)
    if (t < NHEADS) {
        float ern = er[n * NHEADS + t];
        float mx = -INFINITY;
        for (int p = p0; p < p1; p++) {
            float x = el[src[eid[p]] * NHEADS + t] + ern;
            x = (x > 0.0f) ? x : 0.2f * x;
            mx = fmaxf(mx, x);
        }
        float s = 0.0f;
        for (int p = p0; p < p1; p++) {
            float x = el[src[eid[p]] * NHEADS + t] + ern;
            x = (x > 0.0f) ? x : 0.2f * x;
            s += expf(x - mx);
        }
        sh_m[t] = mx;
        sh_invs[t] = (s > 0.0f) ? (1.0f / s) : 1.0f;
    }
    __syncthreads();

    float mh = sh_m[h];
    float invs = sh_invs[h];
    float ern = er[n * NHEADS + h];

    float4 ac = make_float4(0.f, 0.f, 0.f, 0.f);  // conv accum
    float4 ag = make_float4(0.f, 0.f, 0.f, 0.f);  // gat accum
    for (int p = p0; p < p1; p++) {
        int e = eid[p];
        int sn = src[e];
        float4 rc = ((const float4*)(Xc + (size_t)sn * HH))[t];
        float4 rg = ((const float4*)(f + (size_t)sn * HH))[t];
        float x = el[sn * NHEADS + h] + ern;
        x = (x > 0.0f) ? x : 0.2f * x;
        float a = expf(x - mh) * invs;
        ac.x += rc.x; ac.y += rc.y; ac.z += rc.z; ac.w += rc.w;
        ag.x += a * rg.x; ag.y += a * rg.y; ag.z += a * rg.z; ag.w += a * rg.w;
    }

    // conv LN
    float sc = rdi[n];
    float4 bb = ((const float4*)bc)[t];
    float4 v = make_float4(ac.x * sc + bb.x, ac.y * sc + bb.y,
                           ac.z * sc + bb.z, ac.w * sc + bb.w);
    float4 y = ln_elu_core4(v, gc, bec);
    float rx = y.x, ry = y.y, rz = y.z, rw = y.w;

    // gat LN
    bb = ((const float4*)bg)[t];
    v = make_float4(ag.x + bb.x, ag.y + bb.y, ag.z + bb.z, ag.w + bb.w);
    y = ln_elu_core4(v, gg, beg);
    rx += y.x; ry += y.y; rz += y.z; rw += y.w;

    // skip LN
    float4 xs = ((const float4*)(Xs + (size_t)n * HH))[t];
    bb = ((const float4*)bs_)[t];
    v = make_float4(xs.x + bb.x, xs.y + bb.y, xs.z + bb.z, xs.w + bb.w);
    y = ln_elu_core4(v, gs, bes);
    rx += y.x; ry += y.y; rz += y.z; rw += y.w;

    uint4 o;
    o.x = f2tf32(rx); o.y = f2tf32(ry); o.z = f2tf32(rz); o.w = f2tf32(rw);
    ((uint4*)(out32 + (size_t)n * (RR * HH)))[t] = o;
}

// ---------------- GAT attn-score precompute ----------------
__global__ void gat_el_er(const float* __restrict__ f, const float* __restrict__ al,
                          const float* __restrict__ ar, float* __restrict__ el,
                          float* __restrict__ er) {
    int idx = blockIdx.x * blockDim.x + threadIdx.x;
    if (idx >= NN * NHEADS) return;
    int n = idx >> 3;
    int hh = idx & 7;
    const float* fr = f + (size_t)n * HH + hh * DHH;
    const float* a1 = al + hh * DHH;
    const float* a2 = ar + hh * DHH;
    float s1 = 0.0f, s2 = 0.0f;
#pragma unroll 8
    for (int d = 0; d < DHH; d++) {
        float fv = fr[d];
        s1 += fv * a1[d];
        s2 += fv * a2[d];
    }
    el[idx] = s1;
    er[idx] = s2;
}

// ---------------- relation MHA (3 tokens) + mean; writes f32 h and tf32 h32 --
__global__ __launch_bounds__(256) void mha_mean(
    const float* __restrict__ q, const float* __restrict__ k,
    const float* __restrict__ v, float* __restrict__ out,
    unsigned* __restrict__ out32) {
    int n = blockIdx.x;
    int hd = threadIdx.x >> 5;
    int lane = threadIdx.x & 31;
    size_t base = (size_t)n * RR * HH + hd * DHH;
    float qa[RR], qb[RR], ka[RR], kb[RR], va[RR], vb[RR];
#pragma unroll
    for (int r = 0; r < RR; r++) {
        size_t off = base + (size_t)r * HH;
        qa[r] = q[off + lane];
        qb[r] = q[off + lane + 32];
        ka[r] = k[off + lane];
        kb[r] = k[off + lane + 32];
        va[r] = v[off + lane];
        vb[r] = v[off + lane + 32];
    }
    float sc[RR][RR];
#pragma unroll
    for (int r = 0; r < RR; r++)
#pragma unroll
        for (int t = 0; t < RR; t++) {
            float p = qa[r] * ka[t] + qb[r] * kb[t];
#pragma unroll
            for (int o = 16; o > 0; o >>= 1) p += __shfl_xor_sync(0xffffffffu, p, o);
            sc[r][t] = p * 0.125f;
        }
    float w0 = 0.0f, w1 = 0.0f, w2 = 0.0f;
#pragma unroll
    for (int r = 0; r < RR; r++) {
        float mx = fmaxf(sc[r][0], fmaxf(sc[r][1], sc[r][2]));
        float e0 = expf(sc[r][0] - mx);
        float e1 = expf(sc[r][1] - mx);
        float e2 = expf(sc[r][2] - mx);
        float inv = 1.0f / (e0 + e1 + e2);
        w0 += e0 * inv;
        w1 += e1 * inv;
        w2 += e2 * inv;
    }
    const float third = 1.0f / 3.0f;
    float oa = (w0 * va[0] + w1 * va[1] + w2 * va[2]) * third;
    float ob = (w0 * vb[0] + w1 * vb[1] + w2 * vb[2]) * third;
    size_t o0 = (size_t)n * HH + hd * DHH + lane;
    out[o0] = oa;
    out[o0 + 32] = ob;
    out32[o0] = f2tf32(oa);
    out32[o0 + 32] = f2tf32(ob);
}

// ---------------- classifier ----------------
__global__ void classify(const float* __restrict__ h, const float* __restrict__ W,
                         const float* __restrict__ b, float* __restrict__ out) {
    int idx = blockIdx.x * blockDim.x + threadIdx.x;
    if (idx >= NN * NCLSS) return;
    int n = idx / NCLSS;
    int c = idx % NCLSS;
    const float* hr = h + (size_t)n * HH;
    float sum = b[c];
#pragma unroll 8
    for (int j = 0; j < HH; j++) sum += hr[j] * W[j * NCLSS + c];
    out[idx] = sum;
}

// ---------------- launch ----------------
extern "C" void kernel_launch(void* const* d_in, const int* in_sizes, int n_in,
                              void* d_out, int out_size) {
    const float* feature = (const float*)d_in[0];
    const int* src = (const int*)d_in[1];
    const int* dst = (const int*)d_in[2];
    const float* Wc = (const float*)d_in[3];
    const float* bc = (const float*)d_in[4];
    const float* gc = (const float*)d_in[5];
    const float* betac = (const float*)d_in[6];
    const float* Wg = (const float*)d_in[7];
    const float* bg = (const float*)d_in[8];
    const float* al = (const float*)d_in[9];
    const float* ar = (const float*)d_in[10];
    const float* gg = (const float*)d_in[11];
    const float* betag = (const float*)d_in[12];
    const float* Ws = (const float*)d_in[13];
    const float* bs = (const float*)d_in[14];
    const float* gs = (const float*)d_in[15];
    const float* betas = (const float*)d_in[16];
    const float* Wq = (const float*)d_in[17];
    const float* bq = (const float*)d_in[18];
    const float* Wk = (const float*)d_in[19];
    const float* bk = (const float*)d_in[20];
    const float* Wv = (const float*)d_in[21];
    const float* bv = (const float*)d_in[22];
    const float* Wout = (const float*)d_in[23];
    const float* bout = (const float*)d_in[24];
    float* out = (float*)d_out;

    float *p_h, *p_tmp, *p_tmp2, *p_f, *p_q, *p_k, *p_v;
    float *p_rdo, *p_rdi, *p_el, *p_er;
    unsigned *p_h32, *p_stk32, *p_w32;
    int *p_cnt, *p_cur, *p_off, *p_eid;
    cudaGetSymbolAddress((void**)&p_h, g_h);
    cudaGetSymbolAddress((void**)&p_h32, g_h32);
    cudaGetSymbolAddress((void**)&p_tmp, g_tmp);
    cudaGetSymbolAddress((void**)&p_tmp2, g_tmp2);
    cudaGetSymbolAddress((void**)&p_f, g_f);
    cudaGetSymbolAddress((void**)&p_stk32, g_stk32);
    cudaGetSymbolAddress((void**)&p_q, g_q);
    cudaGetSymbolAddress((void**)&p_k, g_k);
    cudaGetSymbolAddress((void**)&p_v, g_v);
    cudaGetSymbolAddress((void**)&p_w32, g_w32);
    cudaGetSymbolAddress((void**)&p_rdo, g_rdo);
    cudaGetSymbolAddress((void**)&p_rdi, g_rdi);
    cudaGetSymbolAddress((void**)&p_el, g_el);
    cudaGetSymbolAddress((void**)&p_er, g_er);
    cudaGetSymbolAddress((void**)&p_cnt, g_cnt);
    cudaGetSymbolAddress((void**)&p_cur, g_cur);
    cudaGetSymbolAddress((void**)&p_off, g_off);
    cudaGetSymbolAddress((void**)&p_eid, g_eid);

    cudaFuncSetAttribute(tf32gemm3, cudaFuncAttributeMaxDynamicSharedMemorySize,
                         GEMM_SMEM);

    const size_t WHH = (size_t)HH * HH;
    unsigned* w32_Wc = p_w32;
    unsigned* w32_Wg = p_w32 + 6 * WHH;
    unsigned* w32_Ws = p_w32 + 12 * WHH;
    unsigned* w32_Wq = p_w32 + 18 * WHH;
    unsigned* w32_Wk = p_w32 + 20 * WHH;
    unsigned* w32_Wv = p_w32 + 22 * WHH;

    {
        int n4 = (int)(6 * WHH / 4);
        int blocks = (n4 + 255) / 256;
        cvt_tf32_vec<<<blocks, 256>>>((const float4*)Wc, (uint4*)w32_Wc, n4);
        cvt_tf32_vec<<<blocks, 256>>>((const float4*)Wg, (uint4*)w32_Wg, n4);
        cvt_tf32_vec<<<blocks, 256>>>((const float4*)Ws, (uint4*)w32_Ws, n4);
        int n4q = (int)(2 * WHH / 4);
        int blocksq = (n4q + 255) / 256;
        cvt_tf32_vec<<<blocksq, 256>>>((const float4*)Wq, (uint4*)w32_Wq, n4q);
        cvt_tf32_vec<<<blocksq, 256>>>((const float4*)Wk, (uint4*)w32_Wk, n4q);
        cvt_tf32_vec<<<blocksq, 256>>>((const float4*)Wv, (uint4*)w32_Wv, n4q);
        int n4f = (int)((size_t)NN * HH / 4);
        cvt_tf32_vec<<<(n4f + 255) / 256, 256>>>((const float4*)feature,
                                                 (uint4*)p_h32, n4f);
    }

    cudaMemsetAsync(p_rdo, 0, (size_t)RR * NN * sizeof(float), 0);
    cudaMemsetAsync(p_rdi, 0, (size_t)RR * NN * sizeof(float), 0);
    cudaMemsetAsync(p_cnt, 0, (size_t)RR * NN * sizeof(int), 0);
    cudaMemsetAsync(p_cur, 0, (size_t)RR * NN * sizeof(int), 0);
    degree_count<<<(RR * EE + 255) / 256, 256>>>(src, dst, p_rdo, p_rdi, p_cnt);
    degree_finalize<<<(RR * NN + 255) / 256, 256>>>(p_rdo, RR * NN);
    degree_finalize<<<(RR * NN + 255) / 256, 256>>>(p_rdi, RR * NN);
    scan_offsets<<<RR, 1024>>>(p_cnt, p_off);
    build_adj<<<(RR * EE + 255) / 256, 256>>>(dst, p_off, p_cur, p_eid);

    const dim3 gemm_grid_n(4, (NN + 127) / 128, 3);
    const dim3 gemm_grid_nr(4, (NN * RR + 127) / 128, 3);
    const int nhd_blocks = (NN * NHEADS + 255) / 256;

    for (int l = 0; l < LL; l++) {
        for (int r = 0; r < RR; r++) {
            const size_t lr = (size_t)(l * RR + r);
            const int* src_r = src + (size_t)r * EE;
            const int* eid_r = p_eid + (size_t)r * EE;
            const int* off_r = p_off + (size_t)r * (NN + 1);

            G3 a3;
            a3.W[0] = w32_Wc + lr * WHH;
            a3.W[1] = w32_Wg + lr * WHH;
            a3.W[2] = w32_Ws + lr * WHH;
            a3.C[0] = p_tmp;
            a3.C[1] = p_f;
            a3.C[2] = p_tmp2;
            a3.rs[0] = p_rdo + (size_t)r * NN;
            a3.rs[1] = nullptr;
            a3.rs[2] = nullptr;
            a3.b[0] = nullptr;
            a3.b[1] = nullptr;
            a3.b[2] = nullptr;
            tf32gemm3<<<gemm_grid_n, 256, GEMM_SMEM>>>(p_h32, a3, NN);

            gat_el_er<<<nhd_blocks, 256>>>(p_f, al + lr * NHEADS * DHH,
                                           ar + lr * NHEADS * DHH, p_el, p_er);

            fused_branches<<<NN, 128>>>(
                eid_r, off_r, src_r, p_tmp, p_f, p_tmp2, p_el, p_er,
                p_rdi + (size_t)r * NN,
                bc + lr * HH, gc + lr * HH, betac + lr * HH,
                bg + lr * HH, gg + lr * HH, betag + lr * HH,
                bs + lr * HH, gs + lr * HH, betas + lr * HH,
                p_stk32 + (size_t)r * HH);
        }

        G3 aq;
        aq.W[0] = w32_Wq + (size_t)l * WHH;
        aq.W[1] = w32_Wk + (size_t)l * WHH;
        aq.W[2] = w32_Wv + (size_t)l * WHH;
        aq.C[0] = p_q;
        aq.C[1] = p_k;
        aq.C[2] = p_v;
        aq.rs[0] = nullptr; aq.rs[1] = nullptr; aq.rs[2] = nullptr;
        aq.b[0] = bq + (size_t)l * HH;
        aq.b[1] = bk + (size_t)l * HH;
        aq.b[2] = bv + (size_t)l * HH;
        tf32gemm3<<<gemm_grid_nr, 256, GEMM_SMEM>>>(p_stk32, aq, NN * RR);

        mha_mean<<<NN, 256>>>(p_q, p_k, p_v, p_h, p_h32);
    }

    classify<<<(NN * NCLSS + 255) / 256, 256>>>(p_h, Wout, bout, out);
}